// round 3
// baseline (speedup 1.0000x reference)
#include <cuda_runtime.h>
#include <math.h>

#define SEQ    256
#define BATCH  256
#define KD     1024   // C_IN * R_IN
#define ND     1024   // C_OUT * R_OUT
#define MX     (SEQ * BATCH)
#define HN     (BATCH * ND)
#define NCTA   128

// x-projections for all timesteps, per gate: [3][SEQ*BATCH][ND] (768 MB scratch)
static __device__ float g_gx[(size_t)3 * MX * ND];
// grid barrier state
static __device__ unsigned g_bar_count;
static __device__ unsigned g_bar_gen;

typedef unsigned long long u64;

__device__ __forceinline__ void unpack2(u64 v, float& lo, float& hi) {
    asm("mov.b64 {%0, %1}, %2;" : "=f"(lo), "=f"(hi) : "l"(v));
}
// Packed fp32x2 FMA (sm_100+): 2 FMA lanes/instr -> 128 FMA/cyc/SM.
__device__ __forceinline__ void ffma2(u64& d, u64 a, u64 b) {
    asm("fma.rn.f32x2 %0, %1, %2, %0;" : "+l"(d) : "l"(a), "l"(b));
}

// ============================================================================
// Phase 1: GX[g][m][n] = sum_k x[m][k] * Wg[n][k] + bg[n]
// Dup-free f32x2-along-K scheme: A,B kept [row][k] in smem, operands loaded
// as ulonglong2 (LDS.128 = 2 k-pairs), accumulators are packed even/odd-k
// partial sums reduced at the end. No pack/dup MOVs in the inner loop.
// Tile: BM=128 x BN=64, BK=16, 256 threads, TM=8 rows x TN=4 cols/thread.
// ============================================================================
__global__ __launch_bounds__(256, 2)
void gemm_gx2(const float* __restrict__ A,
              const float* __restrict__ W0, const float* __restrict__ W1,
              const float* __restrict__ W2,
              const float* __restrict__ b0, const float* __restrict__ b1,
              const float* __restrict__ b2)
{
    constexpr int BM = 128, BN = 64, BK = 16;
    constexpr int RS = BK + 4;               // row stride (floats): 20 ≡ 4 mod 32 banks

    __shared__ alignas(16) float As[BM][RS];
    __shared__ alignas(16) float Bs[BN][RS];

    const int g = blockIdx.z;
    const float* W    = (g == 0) ? W0 : (g == 1) ? W1 : W2;
    const float* bias = (g == 0) ? b0 : (g == 1) ? b1 : b2;
    float* C = g_gx + (size_t)g * ((size_t)MX * ND);

    const int tid = threadIdx.x;
    const int tx  = tid & 15;                // col lane
    const int ty  = tid >> 4;                // row group
    const int m0  = blockIdx.x * BM;
    const int n0  = blockIdx.y * BN;

    const float* Ap = A + (size_t)m0 * KD;
    const float* Wp = W + (size_t)n0 * KD;

    float4 ar[2], br;
    // prologue: stage first K-tile
    #pragma unroll
    for (int i = 0; i < 2; i++) {
        int q = tid + i * 256;               // 0..511
        ar[i] = *(const float4*)(Ap + (size_t)(q >> 2) * KD + (q & 3) * 4);
    }
    br = *(const float4*)(Wp + (size_t)(tid >> 2) * KD + (tid & 3) * 4);

    u64 acc[8][4];
    #pragma unroll
    for (int r = 0; r < 8; r++)
        #pragma unroll
        for (int j = 0; j < 4; j++) acc[r][j] = 0ull;

    for (int kt = 0; kt < KD; kt += BK) {
        #pragma unroll
        for (int i = 0; i < 2; i++) {
            int q = tid + i * 256;
            *(float4*)(&As[q >> 2][(q & 3) * 4]) = ar[i];
        }
        *(float4*)(&Bs[tid >> 2][(tid & 3) * 4]) = br;
        __syncthreads();

        if (kt + BK < KD) {
            #pragma unroll
            for (int i = 0; i < 2; i++) {
                int q = tid + i * 256;
                ar[i] = *(const float4*)(Ap + (size_t)(q >> 2) * KD + (kt + BK) + (q & 3) * 4);
            }
            br = *(const float4*)(Wp + (size_t)(tid >> 2) * KD + (kt + BK) + (tid & 3) * 4);
        }

        #pragma unroll
        for (int q4 = 0; q4 < 4; q4++) {
            ulonglong2 bq[4];
            #pragma unroll
            for (int j = 0; j < 4; j++)
                bq[j] = *(const ulonglong2*)(&Bs[tx + 16 * j][q4 * 4]);
            #pragma unroll
            for (int r = 0; r < 8; r++) {
                ulonglong2 aq = *(const ulonglong2*)(&As[ty * 8 + r][q4 * 4]);
                #pragma unroll
                for (int j = 0; j < 4; j++) {
                    ffma2(acc[r][j], aq.x, bq[j].x);
                    ffma2(acc[r][j], aq.y, bq[j].y);
                }
            }
        }
        __syncthreads();
    }

    // epilogue: reduce packed lanes, add bias, store (cols tx, tx+16, tx+32, tx+48)
    float bv[4];
    #pragma unroll
    for (int j = 0; j < 4; j++) bv[j] = bias[n0 + tx + 16 * j];
    #pragma unroll
    for (int r = 0; r < 8; r++) {
        float* Crow = C + (size_t)(m0 + ty * 8 + r) * ND + n0;
        #pragma unroll
        for (int j = 0; j < 4; j++) {
            float lo, hi;
            unpack2(acc[r][j], lo, hi);
            Crow[tx + 16 * j] = lo + hi + bv[j];
        }
    }
}

// ============================================================================
// Phase 2: persistent fused recurrence.
// 128 CTAs x 256 threads, ~218 KB dyn smem => 1 CTA/SM, all co-resident.
// CTA c: rows r0 = 128*(c&1), n-cols n0 = 16*(c>>1), all 3 gates fused.
// Weights (48 cols x 1024 k) resident in smem for all 256 steps.
// Inner loop: LDS.128 operands (ulonglong2), FFMA2-pipe-bound by construction.
// ============================================================================
#define WSTR 1028                       // Ws row stride (floats): 16B-aligned, ≡4 mod 32 banks
#define ASTR 20                         // As row stride (floats): 16B-aligned, ≡4 mod 32 banks
#define BKC  16                         // K chunk
#define NCHK (KD / BKC)                 // 64 chunks

__global__ void bar_init_kernel() { g_bar_count = 0; g_bar_gen = 0; }

__device__ __forceinline__ float sigm(float v) { return 1.0f / (1.0f + expf(-v)); }

__global__ __launch_bounds__(256, 1)
void gru_persistent(const float* __restrict__ h0,
                    const float* __restrict__ Wrh, const float* __restrict__ brh,
                    const float* __restrict__ Wuh, const float* __restrict__ buh,
                    const float* __restrict__ Wch, const float* __restrict__ bch,
                    float* __restrict__ hseq, float* __restrict__ hlast)
{
    extern __shared__ float smem[];
    float* Ws = smem;                        // [48][WSTR]
    float* As = Ws + 48 * WSTR;              // [2][128][ASTR]  (offset 16B-aligned)
    float* bs = As + 2 * 128 * ASTR;         // [48]

    const int tid = threadIdx.x;
    const int tx  = tid & 15;                // n-col within group
    const int ty  = tid >> 4;                // row group (8 rows each)
    const int c   = blockIdx.x;
    const int r0  = (c & 1) * 128;
    const int n0  = (c >> 1) * 16;

    // ---- load weights once (48 cols x 1024 k, float4, coalesced) ----
    {
        const float* Wg[3] = { Wrh, Wuh, Wch };
        #pragma unroll 4
        for (int i = 0; i < 48; i++) {
            int q   = tid + i * 256;         // float4 index, 48*256 total
            int j48 = q >> 8;                // 0..47
            int k4  = q & 255;               // float4 within row
            int g   = j48 >> 4;
            int j   = j48 & 15;
            float4 v = *(const float4*)(Wg[g] + (size_t)(n0 + j) * KD + k4 * 4);
            *(float4*)(Ws + j48 * WSTR + k4 * 4) = v;
        }
        if (tid < 48) {
            const float* bg = (tid < 16) ? brh : (tid < 32) ? buh : bch;
            bs[tid] = bg[n0 + (tid & 15)];
        }
    }
    __syncthreads();

    u64 acc[3][8];
    #pragma unroll
    for (int g = 0; g < 3; g++)
        #pragma unroll
        for (int r = 0; r < 8; r++) acc[g][r] = 0ull;

    for (int t = 0; t < SEQ; t++) {
        const float* hp = (t == 0) ? h0 : (hseq + (size_t)(t - 1) * HN);

        // ---- prefetch epilogue operands (independent of K loop) ----
        float xg[3][8], hpv[8];
        {
            const int col = n0 + tx;
            #pragma unroll
            for (int r = 0; r < 8; r++) {
                size_t row_g = (size_t)(r0 + ty * 8 + r);
                size_t mrow  = (size_t)t * BATCH + row_g;
                xg[0][r] = g_gx[0 * (size_t)MX * ND + mrow * ND + col];
                xg[1][r] = g_gx[1 * (size_t)MX * ND + mrow * ND + col];
                xg[2][r] = g_gx[2 * (size_t)MX * ND + mrow * ND + col];
                hpv[r]   = hp[row_g * ND + col];
            }
        }

        // ---- h-GEMM over K = 1024 in 16-wide chunks, double-buffered smem ----
        float4 st[2];
        // prefetch chunk 0 (512 float4 / 256 threads = 2 each)
        #pragma unroll
        for (int i = 0; i < 2; i++) {
            int q = tid + i * 256;
            st[i] = *(const float4*)(hp + (size_t)(r0 + (q >> 2)) * KD + (q & 3) * 4);
        }
        #pragma unroll
        for (int i = 0; i < 2; i++) {
            int q = tid + i * 256;
            *(float4*)(As + 0 * 128 * ASTR + (q >> 2) * ASTR + (q & 3) * 4) = st[i];
        }
        __syncthreads();

        for (int kt = 0; kt < NCHK; kt++) {
            const int cur = kt & 1;
            if (kt + 1 < NCHK) {
                #pragma unroll
                for (int i = 0; i < 2; i++) {
                    int q = tid + i * 256;
                    st[i] = *(const float4*)(hp + (size_t)(r0 + (q >> 2)) * KD
                                             + (kt + 1) * BKC + (q & 3) * 4);
                }
            }
            const float* a_base = As + cur * 128 * ASTR + (ty * 8) * ASTR;
            const float* w_base = Ws + tx * WSTR + kt * BKC;
            #pragma unroll
            for (int q4 = 0; q4 < 4; q4++) {
                ulonglong2 w0 = *(const ulonglong2*)(w_base + 0 * 16 * WSTR + q4 * 4);
                ulonglong2 w1 = *(const ulonglong2*)(w_base + 1 * 16 * WSTR + q4 * 4);
                ulonglong2 w2 = *(const ulonglong2*)(w_base + 2 * 16 * WSTR + q4 * 4);
                #pragma unroll
                for (int r = 0; r < 8; r++) {
                    ulonglong2 h2 = *(const ulonglong2*)(a_base + r * ASTR + q4 * 4);
                    ffma2(acc[0][r], h2.x, w0.x);
                    ffma2(acc[0][r], h2.y, w0.y);
                    ffma2(acc[1][r], h2.x, w1.x);
                    ffma2(acc[1][r], h2.y, w1.y);
                    ffma2(acc[2][r], h2.x, w2.x);
                    ffma2(acc[2][r], h2.y, w2.y);
                }
            }
            if (kt + 1 < NCHK) {
                const int nxt = 1 - cur;
                #pragma unroll
                for (int i = 0; i < 2; i++) {
                    int q = tid + i * 256;
                    *(float4*)(As + nxt * 128 * ASTR + (q >> 2) * ASTR + (q & 3) * 4) = st[i];
                }
            }
            __syncthreads();
        }

        // ---- fused gate epilogue ----
        {
            const int col = n0 + tx;
            const float br_ = bs[tx], bu_ = bs[16 + tx], bc_ = bs[32 + tx];
            #pragma unroll
            for (int r = 0; r < 8; r++) {
                float lo, hi, pr, pu, pc;
                unpack2(acc[0][r], lo, hi); pr = lo + hi + br_ + xg[0][r];
                unpack2(acc[1][r], lo, hi); pu = lo + hi + bu_ + xg[1][r];
                unpack2(acc[2][r], lo, hi); pc = lo + hi + bc_;     // h-side c + bch
                acc[0][r] = 0ull; acc[1][r] = 0ull; acc[2][r] = 0ull;

                float rr = sigm(pr);
                float zz = sigm(pu);
                float nn = tanhf(xg[2][r] + rr * pc);               // xg[2] has bcx
                float hn = nn + zz * (hpv[r] - nn);

                size_t row_g = (size_t)(r0 + ty * 8 + r);
                hseq[(size_t)t * HN + row_g * ND + col] = hn;
                if (t == SEQ - 1) hlast[row_g * ND + col] = hn;
            }
        }

        // ---- grid barrier ----
        __syncthreads();
        if (tid == 0) {
            __threadfence();
            unsigned prev = atomicAdd(&g_bar_count, 1u);
            if (prev == NCTA - 1) {
                g_bar_count = 0;
                __threadfence();
                atomicAdd(&g_bar_gen, 1u);
            } else {
                unsigned target = (unsigned)t + 1u;
                while (*(volatile unsigned*)&g_bar_gen < target) { __nanosleep(32); }
            }
        }
        __syncthreads();
    }
}

// ============================================================================
extern "C" void kernel_launch(void* const* d_in, const int* in_sizes, int n_in,
                              void* d_out, int out_size)
{
    const float* x   = (const float*)d_in[0];
    const float* h0  = (const float*)d_in[1];
    const float* Wrx = (const float*)d_in[2];
    const float* brx = (const float*)d_in[3];
    const float* Wrh = (const float*)d_in[4];
    const float* brh = (const float*)d_in[5];
    const float* Wux = (const float*)d_in[6];
    const float* bux = (const float*)d_in[7];
    const float* Wuh = (const float*)d_in[8];
    const float* buh = (const float*)d_in[9];
    const float* Wcx = (const float*)d_in[10];
    const float* bcx = (const float*)d_in[11];
    const float* Wch = (const float*)d_in[12];
    const float* bch = (const float*)d_in[13];

    float* out   = (float*)d_out;
    float* hseq  = out;                               // [SEQ][BATCH][ND]
    float* hlast = out + (size_t)SEQ * BATCH * ND;    // [BATCH][ND]

    // Phase 1: x-projections for all timesteps (3 gates batched in grid.z).
    {
        dim3 grid(MX / 128, ND / 64, 3);
        gemm_gx2<<<grid, 256>>>(x, Wrx, Wux, Wcx, brx, bux, bcx);
    }

    // Phase 2: persistent fused recurrence (single launch for all 256 steps).
    {
        const int smem_bytes = (48 * WSTR + 2 * 128 * ASTR + 64) * 4;
        cudaFuncSetAttribute(gru_persistent,
                             cudaFuncAttributeMaxDynamicSharedMemorySize,
                             smem_bytes);
        bar_init_kernel<<<1, 1>>>();
        gru_persistent<<<NCTA, 256, smem_bytes>>>(h0, Wrh, brh, Wuh, buh, Wch, bch,
                                                  hseq, hlast);
    }
}

// round 6
// speedup vs baseline: 1.3179x; 1.3179x over previous
#include <cuda_runtime.h>
#include <cuda_bf16.h>
#include <stdint.h>
#include <math.h>

#define SEQ    256
#define BATCH  256
#define KD     1024
#define ND     1024
#define MX     (SEQ * BATCH)
#define HN     (BATCH * ND)
#define NCTA   128

// ---------------- device scratch (no runtime allocation allowed) ------------
static __device__ float          g_gx[(size_t)3 * MX * ND];     // 768 MB
static __device__ __nv_bfloat16  g_axhi[(size_t)MX * KD];       // 128 MB
static __device__ __nv_bfloat16  g_axlo[(size_t)MX * KD];       // 128 MB
static __device__ __nv_bfloat16  g_wxhi[(size_t)3 * ND * KD];   // 6 MB
static __device__ __nv_bfloat16  g_wxlo[(size_t)3 * ND * KD];   // 6 MB
static __device__ unsigned g_bar_count;
static __device__ unsigned g_bar_gen;

typedef unsigned long long u64;

__device__ __forceinline__ void unpack2(u64 v, float& lo, float& hi) {
    asm("mov.b64 {%0, %1}, %2;" : "=f"(lo), "=f"(hi) : "l"(v));
}
__device__ __forceinline__ void ffma2(u64& d, u64 a, u64 b) {
    asm("fma.rn.f32x2 %0, %1, %2, %0;" : "+l"(d) : "l"(a), "l"(b));
}
__device__ __forceinline__ uint32_t smem_u32(const void* p) {
    uint32_t a;
    asm("{ .reg .u64 t; cvta.to.shared.u64 t, %1; cvt.u32.u64 %0, t; }"
        : "=r"(a) : "l"(p));
    return a;
}
static __device__ __forceinline__ uint32_t sw128(uint32_t b) {
    return b ^ ((b >> 3) & 0x70);
}

// ---------------- split fp32 -> bf16 hi/lo ----------------------------------
__global__ __launch_bounds__(256)
void split_bf16(const float* __restrict__ src, __nv_bfloat16* __restrict__ hi,
                __nv_bfloat16* __restrict__ lo, int n4)
{
    int i = blockIdx.x * 256 + threadIdx.x;
    if (i >= n4) return;
    float4 v = ((const float4*)src)[i];
    __nv_bfloat16 h0 = __float2bfloat16_rn(v.x);
    __nv_bfloat16 h1 = __float2bfloat16_rn(v.y);
    __nv_bfloat16 h2 = __float2bfloat16_rn(v.z);
    __nv_bfloat16 h3 = __float2bfloat16_rn(v.w);
    __nv_bfloat16 l0 = __float2bfloat16_rn(v.x - __bfloat162float(h0));
    __nv_bfloat16 l1 = __float2bfloat16_rn(v.y - __bfloat162float(h1));
    __nv_bfloat16 l2 = __float2bfloat16_rn(v.z - __bfloat162float(h2));
    __nv_bfloat16 l3 = __float2bfloat16_rn(v.w - __bfloat162float(h3));
    __nv_bfloat162* hp = (__nv_bfloat162*)(hi + (size_t)i * 4);
    __nv_bfloat162* lp = (__nv_bfloat162*)(lo + (size_t)i * 4);
    hp[0] = __nv_bfloat162(h0, h1); hp[1] = __nv_bfloat162(h2, h3);
    lp[0] = __nv_bfloat162(l0, l1); lp[1] = __nv_bfloat162(l2, l3);
}

// ---------------- phase 1: mma.sync (HMMA) bf16-split GEMM ------------------
// gx[g][m][n] = sum over concat-K of Apass[m][k] * Wpass[n][k] + bias_g[n]
// 3 passes (hi*hi, hi*lo, lo*hi) as K' = 3072.  Tile 128x64, chunk 64 bf16.
#define BMT  128
#define BNT  64
#define BKT  64                        // bf16 per chunk = 128 bytes per row
#define NCHT 48                        // 3 passes x 16 chunks
#define ASTAGE 16384                   // 128 rows x 128 B
#define BSTAGE 8192                    // 64 rows x 128 B
#define STG    (ASTAGE + BSTAGE)       // 24576 per stage

__device__ __forceinline__ void ldsm4(uint32_t (&d)[4], uint32_t addr) {
    asm volatile("ldmatrix.sync.aligned.m8n8.x4.shared.b16 {%0,%1,%2,%3}, [%4];"
                 : "=r"(d[0]), "=r"(d[1]), "=r"(d[2]), "=r"(d[3]) : "r"(addr));
}
__device__ __forceinline__ void mma16816(float (&c)[4], const uint32_t (&a)[4],
                                         uint32_t b0, uint32_t b1) {
    asm volatile("mma.sync.aligned.m16n8k16.row.col.f32.bf16.bf16.f32 "
                 "{%0,%1,%2,%3}, {%4,%5,%6,%7}, {%8,%9}, {%0,%1,%2,%3};"
                 : "+f"(c[0]), "+f"(c[1]), "+f"(c[2]), "+f"(c[3])
                 : "r"(a[0]), "r"(a[1]), "r"(a[2]), "r"(a[3]), "r"(b0), "r"(b1));
}

__global__ __launch_bounds__(256)
void gemm_hmma(const float* __restrict__ b0p, const float* __restrict__ b1p,
               const float* __restrict__ b2p)
{
    extern __shared__ char sm[];
    const uint32_t smb = smem_u32(sm);
    const int tid  = threadIdx.x;
    const int lane = tid & 31;
    const int w    = tid >> 5;
    const int wm   = w & 3;            // m block of 32
    const int wn   = w >> 2;           // n block of 32
    const int n0   = blockIdx.x * BNT;
    const int m0   = blockIdx.y * BMT;
    const int g    = blockIdx.z;

    const __nv_bfloat16* ahi = g_axhi + (size_t)m0 * KD;
    const __nv_bfloat16* alo = g_axlo + (size_t)m0 * KD;
    const __nv_bfloat16* whi = g_wxhi + (size_t)g * ND * KD + (size_t)n0 * KD;
    const __nv_bfloat16* wlo = g_wxlo + (size_t)g * ND * KD + (size_t)n0 * KD;

    float acc[2][4][4];
    #pragma unroll
    for (int mi = 0; mi < 2; mi++)
        #pragma unroll
        for (int ni = 0; ni < 4; ni++)
            #pragma unroll
            for (int q = 0; q < 4; q++) acc[mi][ni][q] = 0.0f;

    uint4 ra[4], rb[2];
    // prologue: chunk 0 (pass hi*hi)
    #pragma unroll
    for (int i = 0; i < 4; i++) {
        int q = tid + i * 256;
        ra[i] = *(const uint4*)(ahi + (size_t)(q >> 3) * KD + (q & 7) * 8);
    }
    #pragma unroll
    for (int i = 0; i < 2; i++) {
        int q = tid + i * 256;
        rb[i] = *(const uint4*)(whi + (size_t)(q >> 3) * KD + (q & 7) * 8);
    }
    #pragma unroll
    for (int i = 0; i < 4; i++) {
        int q = tid + i * 256;
        *(uint4*)(sm + sw128((q >> 3) * 128 + (q & 7) * 16)) = ra[i];
    }
    #pragma unroll
    for (int i = 0; i < 2; i++) {
        int q = tid + i * 256;
        *(uint4*)(sm + ASTAGE + sw128((q >> 3) * 128 + (q & 7) * 16)) = rb[i];
    }
    __syncthreads();

    for (int it = 0; it < NCHT; it++) {
        const int cur = it & 1;
        if (it + 1 < NCHT) {
            int p  = (it + 1) >> 4;
            int kc = (it + 1) & 15;
            const __nv_bfloat16* Ap = ((p < 2) ? ahi : alo) + kc * BKT;
            const __nv_bfloat16* Wp = ((p == 1) ? wlo : whi) + kc * BKT;
            #pragma unroll
            for (int i = 0; i < 4; i++) {
                int q = tid + i * 256;
                ra[i] = *(const uint4*)(Ap + (size_t)(q >> 3) * KD + (q & 7) * 8);
            }
            #pragma unroll
            for (int i = 0; i < 2; i++) {
                int q = tid + i * 256;
                rb[i] = *(const uint4*)(Wp + (size_t)(q >> 3) * KD + (q & 7) * 8);
            }
        }

        const uint32_t aBase = smb + cur * STG;
        const uint32_t bBase = smb + cur * STG + ASTAGE;
        #pragma unroll
        for (int kk = 0; kk < 4; kk++) {
            uint32_t af[2][4];
            {
                int tile = lane >> 3, r = lane & 7;
                int kb = kk * 32 + (tile >> 1) * 16;
                #pragma unroll
                for (int mi = 0; mi < 2; mi++) {
                    int row = wm * 32 + mi * 16 + (tile & 1) * 8 + r;
                    ldsm4(af[mi], aBase + sw128((uint32_t)(row * 128 + kb)));
                }
            }
            uint32_t bf[2][4];
            {
                int pair = lane >> 4, khalf = (lane >> 3) & 1, r = lane & 7;
                int kb = kk * 32 + khalf * 16;
                #pragma unroll
                for (int bp = 0; bp < 2; bp++) {
                    int rowN = wn * 32 + bp * 16 + pair * 8 + r;
                    ldsm4(bf[bp], bBase + sw128((uint32_t)(rowN * 128 + kb)));
                }
            }
            #pragma unroll
            for (int mi = 0; mi < 2; mi++)
                #pragma unroll
                for (int ni = 0; ni < 4; ni++)
                    mma16816(acc[mi][ni], af[mi],
                             bf[ni >> 1][(ni & 1) * 2], bf[ni >> 1][(ni & 1) * 2 + 1]);
        }

        if (it + 1 < NCHT) {
            const int nxt = 1 - cur;
            #pragma unroll
            for (int i = 0; i < 4; i++) {
                int q = tid + i * 256;
                *(uint4*)(sm + nxt * STG + sw128((q >> 3) * 128 + (q & 7) * 16)) = ra[i];
            }
            #pragma unroll
            for (int i = 0; i < 2; i++) {
                int q = tid + i * 256;
                *(uint4*)(sm + nxt * STG + ASTAGE + sw128((q >> 3) * 128 + (q & 7) * 16)) = rb[i];
            }
            __syncthreads();
        }
    }

    // epilogue: bias + direct global stores (float2 per fragment row)
    const float* bias = (g == 0) ? b0p : (g == 1) ? b1p : b2p;
    float* C = g_gx + (size_t)g * MX * ND;
    #pragma unroll
    for (int ni = 0; ni < 4; ni++) {
        int col = n0 + wn * 32 + ni * 8 + (lane & 3) * 2;
        float2 bv = *(const float2*)(bias + col);
        #pragma unroll
        for (int mi = 0; mi < 2; mi++) {
            int row = m0 + wm * 32 + mi * 16 + (lane >> 2);
            float2 v0 = make_float2(acc[mi][ni][0] + bv.x, acc[mi][ni][1] + bv.y);
            float2 v1 = make_float2(acc[mi][ni][2] + bv.x, acc[mi][ni][3] + bv.y);
            *(float2*)(C + (size_t)row * ND + col)       = v0;
            *(float2*)(C + (size_t)(row + 8) * ND + col) = v1;
        }
    }
}

// ---------------- phase 2: persistent fused recurrence (round-2 proven) -----
#define WSTR 1026
#define ASTR 18
#define BKC  16
#define NCHK (KD / BKC)

__global__ void bar_init_kernel() { g_bar_count = 0; g_bar_gen = 0; }

__device__ __forceinline__ float sigm(float v) { return 1.0f / (1.0f + expf(-v)); }

__global__ __launch_bounds__(256, 1)
void gru_persistent(const float* __restrict__ h0,
                    const float* __restrict__ Wrh, const float* __restrict__ brh,
                    const float* __restrict__ Wuh, const float* __restrict__ buh,
                    const float* __restrict__ Wch, const float* __restrict__ bch,
                    float* __restrict__ hseq, float* __restrict__ hlast)
{
    extern __shared__ float smem[];
    float* Ws = smem;                        // [48][WSTR]
    float* As = Ws + 48 * WSTR;              // [2][128][ASTR]
    float* bs = As + 2 * 128 * ASTR;         // [48]

    const int tid = threadIdx.x;
    const int tx  = tid & 15;
    const int ty  = tid >> 4;
    const int c   = blockIdx.x;
    const int r0  = (c & 1) * 128;
    const int n0  = (c >> 1) * 16;

    {
        const float* Wg[3] = { Wrh, Wuh, Wch };
        #pragma unroll 4
        for (int i = 0; i < 96; i++) {
            int q   = tid + i * 256;
            int j48 = q >> 9;
            int k2  = q & 511;
            int g   = j48 >> 4;
            int j   = j48 & 15;
            float2 v = *(const float2*)(Wg[g] + (size_t)(n0 + j) * KD + k2 * 2);
            *(float2*)(Ws + j48 * WSTR + k2 * 2) = v;
        }
        if (tid < 48) {
            const float* bg = (tid < 16) ? brh : (tid < 32) ? buh : bch;
            bs[tid] = bg[n0 + (tid & 15)];
        }
    }
    __syncthreads();

    u64 acc[3][8];
    #pragma unroll
    for (int g = 0; g < 3; g++)
        #pragma unroll
        for (int r = 0; r < 8; r++) acc[g][r] = 0ull;

    for (int t = 0; t < SEQ; t++) {
        const float* hp = (t == 0) ? h0 : (hseq + (size_t)(t - 1) * HN);

        float xg[3][8], hpv[8];
        {
            const int col = n0 + tx;
            #pragma unroll
            for (int r = 0; r < 8; r++) {
                size_t row_g = (size_t)(r0 + ty * 8 + r);
                size_t mrow  = (size_t)t * BATCH + row_g;
                xg[0][r] = g_gx[0 * (size_t)MX * ND + mrow * ND + col];
                xg[1][r] = g_gx[1 * (size_t)MX * ND + mrow * ND + col];
                xg[2][r] = g_gx[2 * (size_t)MX * ND + mrow * ND + col];
                hpv[r]   = hp[row_g * ND + col];
            }
        }

        float2 st[4];
        #pragma unroll
        for (int i = 0; i < 4; i++) {
            int q = tid + i * 256;
            st[i] = *(const float2*)(hp + (size_t)(r0 + (q >> 3)) * KD + (q & 7) * 2);
        }
        #pragma unroll
        for (int i = 0; i < 4; i++) {
            int q = tid + i * 256;
            *(float2*)(As + 0 * 128 * ASTR + (q >> 3) * ASTR + (q & 7) * 2) = st[i];
        }
        __syncthreads();

        for (int kt = 0; kt < NCHK; kt++) {
            const int cur = kt & 1;
            if (kt + 1 < NCHK) {
                #pragma unroll
                for (int i = 0; i < 4; i++) {
                    int q = tid + i * 256;
                    st[i] = *(const float2*)(hp + (size_t)(r0 + (q >> 3)) * KD
                                             + (kt + 1) * BKC + (q & 7) * 2);
                }
            }
            const float* a_base = As + cur * 128 * ASTR + (ty * 8) * ASTR;
            const float* w_base = Ws + tx * WSTR + kt * BKC;
            #pragma unroll
            for (int kp = 0; kp < 8; kp++) {
                u64 w0 = *(const u64*)(w_base + 0 * 16 * WSTR + 2 * kp);
                u64 w1 = *(const u64*)(w_base + 1 * 16 * WSTR + 2 * kp);
                u64 w2 = *(const u64*)(w_base + 2 * 16 * WSTR + 2 * kp);
                #pragma unroll
                for (int r = 0; r < 8; r++) {
                    u64 h2 = *(const u64*)(a_base + r * ASTR + 2 * kp);
                    ffma2(acc[0][r], h2, w0);
                    ffma2(acc[1][r], h2, w1);
                    ffma2(acc[2][r], h2, w2);
                }
            }
            if (kt + 1 < NCHK) {
                const int nxt = 1 - cur;
                #pragma unroll
                for (int i = 0; i < 4; i++) {
                    int q = tid + i * 256;
                    *(float2*)(As + nxt * 128 * ASTR + (q >> 3) * ASTR + (q & 7) * 2) = st[i];
                }
            }
            __syncthreads();
        }

        {
            const int col = n0 + tx;
            const float br_ = bs[tx], bu_ = bs[16 + tx], bc_ = bs[32 + tx];
            #pragma unroll
            for (int r = 0; r < 8; r++) {
                float lo, hi, pr, pu, pc;
                unpack2(acc[0][r], lo, hi); pr = lo + hi + br_ + xg[0][r];
                unpack2(acc[1][r], lo, hi); pu = lo + hi + bu_ + xg[1][r];
                unpack2(acc[2][r], lo, hi); pc = lo + hi + bc_;
                acc[0][r] = 0ull; acc[1][r] = 0ull; acc[2][r] = 0ull;

                float rr = sigm(pr);
                float zz = sigm(pu);
                float nn = tanhf(xg[2][r] + rr * pc);
                float hn = nn + zz * (hpv[r] - nn);

                size_t row_g = (size_t)(r0 + ty * 8 + r);
                hseq[(size_t)t * HN + row_g * ND + col] = hn;
                if (t == SEQ - 1) hlast[row_g * ND + col] = hn;
            }
        }

        __syncthreads();
        if (tid == 0) {
            __threadfence();
            unsigned prev = atomicAdd(&g_bar_count, 1u);
            if (prev == NCTA - 1) {
                g_bar_count = 0;
                __threadfence();
                atomicAdd(&g_bar_gen, 1u);
            } else {
                unsigned target = (unsigned)t + 1u;
                while (*(volatile unsigned*)&g_bar_gen < target) { __nanosleep(32); }
            }
        }
        __syncthreads();
    }
}

// ============================================================================
extern "C" void kernel_launch(void* const* d_in, const int* in_sizes, int n_in,
                              void* d_out, int out_size)
{
    const float* x   = (const float*)d_in[0];
    const float* h0  = (const float*)d_in[1];
    const float* Wrx = (const float*)d_in[2];
    const float* brx = (const float*)d_in[3];
    const float* Wrh = (const float*)d_in[4];
    const float* brh = (const float*)d_in[5];
    const float* Wux = (const float*)d_in[6];
    const float* bux = (const float*)d_in[7];
    const float* Wuh = (const float*)d_in[8];
    const float* buh = (const float*)d_in[9];
    const float* Wcx = (const float*)d_in[10];
    const float* bcx = (const float*)d_in[11];
    const float* Wch = (const float*)d_in[12];
    const float* bch = (const float*)d_in[13];

    float* out   = (float*)d_out;
    float* hseq  = out;
    float* hlast = out + (size_t)SEQ * BATCH * ND;

    __nv_bfloat16 *axhi, *axlo, *wxhi, *wxlo;
    cudaGetSymbolAddress((void**)&axhi, g_axhi);
    cudaGetSymbolAddress((void**)&axlo, g_axlo);
    cudaGetSymbolAddress((void**)&wxhi, g_wxhi);
    cudaGetSymbolAddress((void**)&wxlo, g_wxlo);

    // Phase 0: split x and x-weights into bf16 hi/lo.
    {
        int n4 = MX * KD / 4;
        split_bf16<<<(n4 + 255) / 256, 256>>>(x, axhi, axlo, n4);
        int w4 = ND * KD / 4;
        split_bf16<<<(w4 + 255) / 256, 256>>>(Wrx, wxhi, wxlo, w4);
        split_bf16<<<(w4 + 255) / 256, 256>>>(Wux, wxhi + (size_t)ND * KD,
                                              wxlo + (size_t)ND * KD, w4);
        split_bf16<<<(w4 + 255) / 256, 256>>>(Wcx, wxhi + (size_t)2 * ND * KD,
                                              wxlo + (size_t)2 * ND * KD, w4);
    }

    // Phase 1: HMMA x-projections (3 gates, split-bf16, fp32 accum).
    {
        const int smem_bytes = 2 * STG;   // 49152
        cudaFuncSetAttribute(gemm_hmma,
                             cudaFuncAttributeMaxDynamicSharedMemorySize, smem_bytes);
        dim3 grid(ND / BNT, MX / BMT, 3);
        gemm_hmma<<<grid, 256, smem_bytes>>>(brx, bux, bcx);
    }

    // Phase 2: persistent fused recurrence.
    {
        const int smem_bytes = (48 * WSTR + 2 * 128 * ASTR + 64) * 4;
        cudaFuncSetAttribute(gru_persistent,
                             cudaFuncAttributeMaxDynamicSharedMemorySize, smem_bytes);
        bar_init_kernel<<<1, 1>>>();
        gru_persistent<<<NCTA, 256, smem_bytes>>>(h0, Wrh, brh, Wuh, buh, Wch, bch,
                                                  hseq, hlast);
    }
}

// round 7
// speedup vs baseline: 2.3544x; 1.7865x over previous
#include <cuda_runtime.h>
#include <cuda_bf16.h>
#include <stdint.h>
#include <math.h>

#define SEQ    256
#define BATCH  256
#define KD     1024
#define ND     1024
#define MX     (SEQ * BATCH)
#define HN     (BATCH * ND)
#define NCTA   128

// ---------------- device scratch (no runtime allocation allowed) ------------
static __device__ float          g_gx[(size_t)3 * MX * ND];     // 768 MB
static __device__ __nv_bfloat16  g_axhi[(size_t)MX * KD];       // 128 MB
static __device__ __nv_bfloat16  g_axlo[(size_t)MX * KD];       // 128 MB
static __device__ __nv_bfloat16  g_wxhi[(size_t)3 * ND * KD];   // 6 MB
static __device__ __nv_bfloat16  g_wxlo[(size_t)3 * ND * KD];   // 6 MB
static __device__ __nv_bfloat16  g_wph[(size_t)3 * ND * KD];    // packed Wh hi
static __device__ __nv_bfloat16  g_wpl[(size_t)3 * ND * KD];    // packed Wh lo
static __device__ __nv_bfloat16  g_hhi[(size_t)BATCH * KD];     // h_t hi
static __device__ __nv_bfloat16  g_hlo[(size_t)BATCH * KD];     // h_t lo
static __device__ unsigned g_bar_count;
static __device__ unsigned g_bar_gen;

__device__ __forceinline__ uint32_t smem_u32(const void* p) {
    uint32_t a;
    asm("{ .reg .u64 t; cvta.to.shared.u64 t, %1; cvt.u32.u64 %0, t; }"
        : "=r"(a) : "l"(p));
    return a;
}
static __device__ __forceinline__ uint32_t sw128(uint32_t b) {
    return b ^ ((b >> 3) & 0x70);
}
__device__ __forceinline__ void ldsm4(uint32_t (&d)[4], uint32_t addr) {
    asm volatile("ldmatrix.sync.aligned.m8n8.x4.shared.b16 {%0,%1,%2,%3}, [%4];"
                 : "=r"(d[0]), "=r"(d[1]), "=r"(d[2]), "=r"(d[3]) : "r"(addr));
}
__device__ __forceinline__ void mma16816(float (&c)[4], const uint32_t (&a)[4],
                                         uint32_t b0, uint32_t b1) {
    asm volatile("mma.sync.aligned.m16n8k16.row.col.f32.bf16.bf16.f32 "
                 "{%0,%1,%2,%3}, {%4,%5,%6,%7}, {%8,%9}, {%0,%1,%2,%3};"
                 : "+f"(c[0]), "+f"(c[1]), "+f"(c[2]), "+f"(c[3])
                 : "r"(a[0]), "r"(a[1]), "r"(a[2]), "r"(a[3]), "r"(b0), "r"(b1));
}
__device__ __forceinline__ void cpa16(uint32_t smaddr, const void* g) {
    asm volatile("cp.async.cg.shared.global [%0], [%1], 16;" :: "r"(smaddr), "l"(g));
}
#define CPA_COMMIT() asm volatile("cp.async.commit_group;" ::: "memory")
template<int N> __device__ __forceinline__ void cp_wait() {
    asm volatile("cp.async.wait_group %0;" :: "n"(N) : "memory");
}
__device__ __forceinline__ float sigm(float v) { return 1.0f / (1.0f + expf(-v)); }

// ---------------- split fp32 -> bf16 hi/lo ----------------------------------
__global__ __launch_bounds__(256)
void split_bf16(const float* __restrict__ src, __nv_bfloat16* __restrict__ hi,
                __nv_bfloat16* __restrict__ lo, int n4)
{
    int i = blockIdx.x * 256 + threadIdx.x;
    if (i >= n4) return;
    float4 v = ((const float4*)src)[i];
    __nv_bfloat16 h0 = __float2bfloat16_rn(v.x);
    __nv_bfloat16 h1 = __float2bfloat16_rn(v.y);
    __nv_bfloat16 h2 = __float2bfloat16_rn(v.z);
    __nv_bfloat16 h3 = __float2bfloat16_rn(v.w);
    __nv_bfloat16 l0 = __float2bfloat16_rn(v.x - __bfloat162float(h0));
    __nv_bfloat16 l1 = __float2bfloat16_rn(v.y - __bfloat162float(h1));
    __nv_bfloat16 l2 = __float2bfloat16_rn(v.z - __bfloat162float(h2));
    __nv_bfloat16 l3 = __float2bfloat16_rn(v.w - __bfloat162float(h3));
    __nv_bfloat162* hp = (__nv_bfloat162*)(hi + (size_t)i * 4);
    __nv_bfloat162* lp = (__nv_bfloat162*)(lo + (size_t)i * 4);
    hp[0] = __nv_bfloat162(h0, h1); hp[1] = __nv_bfloat162(h2, h3);
    lp[0] = __nv_bfloat162(l0, l1); lp[1] = __nv_bfloat162(l2, l3);
}

// pack Wh gate g into [jg][3*32][1024] block layout, split hi/lo
__global__ __launch_bounds__(256)
void pack_wh(const float* __restrict__ W, __nv_bfloat16* __restrict__ ph,
             __nv_bfloat16* __restrict__ pl, int g)
{
    int i = blockIdx.x * 256 + threadIdx.x;    // float4 index over ND*KD/4
    if (i >= ND * KD / 4) return;
    int n  = i >> 8;
    int k4 = i & 255;
    float4 v = *(const float4*)(W + (size_t)n * KD + k4 * 4);
    size_t drow = (size_t)((n >> 5) * 96 + g * 32 + (n & 31));
    __nv_bfloat16 h0 = __float2bfloat16_rn(v.x);
    __nv_bfloat16 h1 = __float2bfloat16_rn(v.y);
    __nv_bfloat16 h2 = __float2bfloat16_rn(v.z);
    __nv_bfloat16 h3 = __float2bfloat16_rn(v.w);
    __nv_bfloat16 l0 = __float2bfloat16_rn(v.x - __bfloat162float(h0));
    __nv_bfloat16 l1 = __float2bfloat16_rn(v.y - __bfloat162float(h1));
    __nv_bfloat16 l2 = __float2bfloat16_rn(v.z - __bfloat162float(h2));
    __nv_bfloat16 l3 = __float2bfloat16_rn(v.w - __bfloat162float(h3));
    __nv_bfloat162* hp = (__nv_bfloat162*)(ph + drow * KD + k4 * 4);
    __nv_bfloat162* lp = (__nv_bfloat162*)(pl + drow * KD + k4 * 4);
    hp[0] = __nv_bfloat162(h0, h1); hp[1] = __nv_bfloat162(h2, h3);
    lp[0] = __nv_bfloat162(l0, l1); lp[1] = __nv_bfloat162(l2, l3);
}

// ---------------- phase 1: mma.sync (HMMA) bf16-split GEMM (round-6 proven) -
#define BMT  128
#define BNT  64
#define BKT  64
#define NCHT 48
#define ASTAGE 16384
#define BSTAGE 8192
#define STG    (ASTAGE + BSTAGE)

__global__ __launch_bounds__(256)
void gemm_hmma(const float* __restrict__ b0p, const float* __restrict__ b1p,
               const float* __restrict__ b2p)
{
    extern __shared__ char sm[];
    const uint32_t smb = smem_u32(sm);
    const int tid  = threadIdx.x;
    const int lane = tid & 31;
    const int w    = tid >> 5;
    const int wm   = w & 3;
    const int wn   = w >> 2;
    const int n0   = blockIdx.x * BNT;
    const int m0   = blockIdx.y * BMT;
    const int g    = blockIdx.z;

    const __nv_bfloat16* ahi = g_axhi + (size_t)m0 * KD;
    const __nv_bfloat16* alo = g_axlo + (size_t)m0 * KD;
    const __nv_bfloat16* whi = g_wxhi + (size_t)g * ND * KD + (size_t)n0 * KD;
    const __nv_bfloat16* wlo = g_wxlo + (size_t)g * ND * KD + (size_t)n0 * KD;

    float acc[2][4][4];
    #pragma unroll
    for (int mi = 0; mi < 2; mi++)
        #pragma unroll
        for (int ni = 0; ni < 4; ni++)
            #pragma unroll
            for (int q = 0; q < 4; q++) acc[mi][ni][q] = 0.0f;

    uint4 ra[4], rb[2];
    #pragma unroll
    for (int i = 0; i < 4; i++) {
        int q = tid + i * 256;
        ra[i] = *(const uint4*)(ahi + (size_t)(q >> 3) * KD + (q & 7) * 8);
    }
    #pragma unroll
    for (int i = 0; i < 2; i++) {
        int q = tid + i * 256;
        rb[i] = *(const uint4*)(whi + (size_t)(q >> 3) * KD + (q & 7) * 8);
    }
    #pragma unroll
    for (int i = 0; i < 4; i++) {
        int q = tid + i * 256;
        *(uint4*)(sm + sw128((q >> 3) * 128 + (q & 7) * 16)) = ra[i];
    }
    #pragma unroll
    for (int i = 0; i < 2; i++) {
        int q = tid + i * 256;
        *(uint4*)(sm + ASTAGE + sw128((q >> 3) * 128 + (q & 7) * 16)) = rb[i];
    }
    __syncthreads();

    for (int it = 0; it < NCHT; it++) {
        const int cur = it & 1;
        if (it + 1 < NCHT) {
            int p  = (it + 1) >> 4;
            int kc = (it + 1) & 15;
            const __nv_bfloat16* Ap = ((p < 2) ? ahi : alo) + kc * BKT;
            const __nv_bfloat16* Wp = ((p == 1) ? wlo : whi) + kc * BKT;
            #pragma unroll
            for (int i = 0; i < 4; i++) {
                int q = tid + i * 256;
                ra[i] = *(const uint4*)(Ap + (size_t)(q >> 3) * KD + (q & 7) * 8);
            }
            #pragma unroll
            for (int i = 0; i < 2; i++) {
                int q = tid + i * 256;
                rb[i] = *(const uint4*)(Wp + (size_t)(q >> 3) * KD + (q & 7) * 8);
            }
        }

        const uint32_t aBase = smb + cur * STG;
        const uint32_t bBase = smb + cur * STG + ASTAGE;
        #pragma unroll
        for (int kk = 0; kk < 4; kk++) {
            uint32_t af[2][4];
            {
                int tile = lane >> 3, r = lane & 7;
                int kb = kk * 32 + (tile >> 1) * 16;
                #pragma unroll
                for (int mi = 0; mi < 2; mi++) {
                    int row = wm * 32 + mi * 16 + (tile & 1) * 8 + r;
                    ldsm4(af[mi], aBase + sw128((uint32_t)(row * 128 + kb)));
                }
            }
            uint32_t bfr[2][4];
            {
                int pair = lane >> 4, khalf = (lane >> 3) & 1, r = lane & 7;
                int kb = kk * 32 + khalf * 16;
                #pragma unroll
                for (int bp = 0; bp < 2; bp++) {
                    int rowN = wn * 32 + bp * 16 + pair * 8 + r;
                    ldsm4(bfr[bp], bBase + sw128((uint32_t)(rowN * 128 + kb)));
                }
            }
            #pragma unroll
            for (int mi = 0; mi < 2; mi++)
                #pragma unroll
                for (int ni = 0; ni < 4; ni++)
                    mma16816(acc[mi][ni], af[mi],
                             bfr[ni >> 1][(ni & 1) * 2], bfr[ni >> 1][(ni & 1) * 2 + 1]);
        }

        if (it + 1 < NCHT) {
            const int nxt = 1 - cur;
            #pragma unroll
            for (int i = 0; i < 4; i++) {
                int q = tid + i * 256;
                *(uint4*)(sm + nxt * STG + sw128((q >> 3) * 128 + (q & 7) * 16)) = ra[i];
            }
            #pragma unroll
            for (int i = 0; i < 2; i++) {
                int q = tid + i * 256;
                *(uint4*)(sm + nxt * STG + ASTAGE + sw128((q >> 3) * 128 + (q & 7) * 16)) = rb[i];
            }
            __syncthreads();
        }
    }

    const float* bias = (g == 0) ? b0p : (g == 1) ? b1p : b2p;
    float* C = g_gx + (size_t)g * MX * ND;
    #pragma unroll
    for (int ni = 0; ni < 4; ni++) {
        int col = n0 + wn * 32 + ni * 8 + (lane & 3) * 2;
        float2 bv = *(const float2*)(bias + col);
        #pragma unroll
        for (int mi = 0; mi < 2; mi++) {
            int row = m0 + wm * 32 + mi * 16 + (lane >> 2);
            float2 v0 = make_float2(acc[mi][ni][0] + bv.x, acc[mi][ni][1] + bv.y);
            float2 v1 = make_float2(acc[mi][ni][2] + bv.x, acc[mi][ni][3] + bv.y);
            *(float2*)(C + (size_t)row * ND + col)       = v0;
            *(float2*)(C + (size_t)(row + 8) * ND + col) = v1;
        }
    }
}

// ---------------- phase 2: persistent HMMA recurrence ----------------------
// 128 CTAs (4 m-tiles x 32 j-groups) x 128 threads, all co-resident.
// Per step: [64 x 96] = h[64,1024] x Wpacked[96,1024]^T, 3-pass split-bf16,
// cp.async 3-stage pipeline, fused gate epilogue, software grid barrier.
#define RST   40960                       // stage bytes: AH 8K | AL 8K | BH 12K | BL 12K
#define OFF_AL 8192
#define OFF_BH 16384
#define OFF_BL 28672
#define GH_OFF (3 * RST)                  // fp32 gh tile [64][100]
#define HX_OFF (GH_OFF + 25600)           // fp32 [4][64][32]: gx r,u,c + hprev
#define SM2_TOTAL (HX_OFF + 32768)        // 181248 bytes

__global__ void bar_init_kernel() { g_bar_count = 0; g_bar_gen = 0; }

__global__ __launch_bounds__(128, 1)
void gru_persistent(const float* __restrict__ h0,
                    const float* __restrict__ brh, const float* __restrict__ buh,
                    const float* __restrict__ bch,
                    float* __restrict__ hseq, float* __restrict__ hlast)
{
    extern __shared__ char sm[];
    const uint32_t smb = smem_u32(sm);
    float* ghs = (float*)(sm + GH_OFF);
    float* hxs = (float*)(sm + HX_OFF);

    const int tid  = threadIdx.x;
    const int lane = tid & 31;
    const int w    = tid >> 5;
    const int wm   = w & 1;                // m half (32 rows)
    const int wn   = w >> 1;               // n half (48 cols)
    const int c    = blockIdx.x;
    const int r0   = (c & 3) * 64;         // batch rows
    const int jg   = c >> 2;               // j-group
    const int n0   = jg * 32;

    const __nv_bfloat16* wph = g_wph + (size_t)(jg * 96) * KD;
    const __nv_bfloat16* wpl = g_wpl + (size_t)(jg * 96) * KD;
    const __nv_bfloat16* hhi = g_hhi + (size_t)r0 * KD;
    const __nv_bfloat16* hlo = g_hlo + (size_t)r0 * KD;

    // per-thread gate column and biases
    const int jj = tid & 31;
    const int rg = tid >> 5;
    const float br_ = brh[n0 + jj], bu_ = buh[n0 + jj], bc_ = bch[n0 + jj];

    float acc[2][6][4];

    for (int t = 0; t < SEQ; t++) {
        const float* hp = (t == 0) ? h0 : (hseq + (size_t)(t - 1) * HN);

        #pragma unroll
        for (int mi = 0; mi < 2; mi++)
            #pragma unroll
            for (int ni = 0; ni < 6; ni++)
                #pragma unroll
                for (int q = 0; q < 4; q++) acc[mi][ni][q] = 0.0f;

        // ---- issue chunk 0 + epilogue operands (group 0) ----
        {
            uint32_t stg = smb;
            #pragma unroll
            for (int i = 0; i < 4; i++) {
                int q = tid + i * 128; int row = q >> 3, kq = q & 7;
                uint32_t d = stg + sw128((uint32_t)(row * 128 + kq * 16));
                cpa16(d,          hhi + (size_t)row * KD + kq * 8);
                cpa16(d + OFF_AL, hlo + (size_t)row * KD + kq * 8);
            }
            #pragma unroll
            for (int i = 0; i < 6; i++) {
                int q = tid + i * 128; int row = q >> 3, kq = q & 7;
                uint32_t d = smb + OFF_BH + sw128((uint32_t)(row * 128 + kq * 16));
                cpa16(d,                    wph + (size_t)row * KD + kq * 8);
                cpa16(d + (OFF_BL - OFF_BH), wpl + (size_t)row * KD + kq * 8);
            }
            uint32_t hxb = smb + HX_OFF;
            #pragma unroll
            for (int g = 0; g < 3; g++) {
                const float* src = g_gx + (size_t)g * MX * ND
                                 + ((size_t)t * BATCH + r0) * ND + n0;
                #pragma unroll
                for (int i = 0; i < 4; i++) {
                    int q = tid + i * 128; int row = q >> 3, j4 = q & 7;
                    cpa16(hxb + g * 8192 + row * 128 + j4 * 16,
                          src + (size_t)row * ND + j4 * 4);
                }
            }
            #pragma unroll
            for (int i = 0; i < 4; i++) {
                int q = tid + i * 128; int row = q >> 3, j4 = q & 7;
                cpa16(hxb + 3 * 8192 + row * 128 + j4 * 16,
                      hp + (size_t)(r0 + row) * ND + n0 + j4 * 4);
            }
            CPA_COMMIT();
        }
        // ---- issue chunk 1 (group 1) ----
        {
            uint32_t stg = smb + RST;
            #pragma unroll
            for (int i = 0; i < 4; i++) {
                int q = tid + i * 128; int row = q >> 3, kq = q & 7;
                uint32_t d = stg + sw128((uint32_t)(row * 128 + kq * 16));
                cpa16(d,          hhi + (size_t)row * KD + 64 + kq * 8);
                cpa16(d + OFF_AL, hlo + (size_t)row * KD + 64 + kq * 8);
            }
            #pragma unroll
            for (int i = 0; i < 6; i++) {
                int q = tid + i * 128; int row = q >> 3, kq = q & 7;
                uint32_t d = stg + OFF_BH + sw128((uint32_t)(row * 128 + kq * 16));
                cpa16(d,                    wph + (size_t)row * KD + 64 + kq * 8);
                cpa16(d + (OFF_BL - OFF_BH), wpl + (size_t)row * KD + 64 + kq * 8);
            }
            CPA_COMMIT();
        }

        // ---- K loop: 16 chunks of 64 ----
        for (int kt = 0; kt < 16; kt++) {
            if (kt < 15) cp_wait<1>(); else cp_wait<0>();
            __syncthreads();
            if (kt + 2 < 16) {
                uint32_t stg = smb + ((kt + 2) % 3) * RST;
                int kb = (kt + 2) * 64;
                #pragma unroll
                for (int i = 0; i < 4; i++) {
                    int q = tid + i * 128; int row = q >> 3, kq = q & 7;
                    uint32_t d = stg + sw128((uint32_t)(row * 128 + kq * 16));
                    cpa16(d,          hhi + (size_t)row * KD + kb + kq * 8);
                    cpa16(d + OFF_AL, hlo + (size_t)row * KD + kb + kq * 8);
                }
                #pragma unroll
                for (int i = 0; i < 6; i++) {
                    int q = tid + i * 128; int row = q >> 3, kq = q & 7;
                    uint32_t d = stg + OFF_BH + sw128((uint32_t)(row * 128 + kq * 16));
                    cpa16(d,                    wph + (size_t)row * KD + kb + kq * 8);
                    cpa16(d + (OFF_BL - OFF_BH), wpl + (size_t)row * KD + kb + kq * 8);
                }
                CPA_COMMIT();
            }
            const uint32_t stg = smb + (kt % 3) * RST;
            #pragma unroll
            for (int kk = 0; kk < 4; kk++) {
                uint32_t ah[2][4], al[2][4], bh[3][4], bl[3][4];
                {
                    int tile = lane >> 3, r = lane & 7;
                    int kb = kk * 32 + (tile >> 1) * 16;
                    #pragma unroll
                    for (int mi = 0; mi < 2; mi++) {
                        uint32_t sa = sw128((uint32_t)((wm * 32 + mi * 16 + (tile & 1) * 8 + r) * 128 + kb));
                        ldsm4(ah[mi], stg + sa);
                        ldsm4(al[mi], stg + OFF_AL + sa);
                    }
                }
                {
                    int pair = lane >> 4, khalf = (lane >> 3) & 1, r = lane & 7;
                    int kb = kk * 32 + khalf * 16;
                    #pragma unroll
                    for (int bp = 0; bp < 3; bp++) {
                        uint32_t sb = sw128((uint32_t)((wn * 48 + bp * 16 + pair * 8 + r) * 128 + kb));
                        ldsm4(bh[bp], stg + OFF_BH + sb);
                        ldsm4(bl[bp], stg + OFF_BL + sb);
                    }
                }
                #pragma unroll
                for (int mi = 0; mi < 2; mi++)
                    #pragma unroll
                    for (int ni = 0; ni < 6; ni++) {
                        uint32_t bh0 = bh[ni >> 1][(ni & 1) * 2], bh1 = bh[ni >> 1][(ni & 1) * 2 + 1];
                        uint32_t bl0 = bl[ni >> 1][(ni & 1) * 2], bl1 = bl[ni >> 1][(ni & 1) * 2 + 1];
                        mma16816(acc[mi][ni], ah[mi], bh0, bh1);
                        mma16816(acc[mi][ni], al[mi], bh0, bh1);
                        mma16816(acc[mi][ni], ah[mi], bl0, bl1);
                    }
            }
        }

        // ---- dump accumulators to smem tile [64][100] ----
        #pragma unroll
        for (int mi = 0; mi < 2; mi++)
            #pragma unroll
            for (int ni = 0; ni < 6; ni++) {
                int col = wn * 48 + ni * 8 + (lane & 3) * 2;
                int row = wm * 32 + mi * 16 + (lane >> 2);
                *(float2*)(ghs + row * 100 + col)       = make_float2(acc[mi][ni][0], acc[mi][ni][1]);
                *(float2*)(ghs + (row + 8) * 100 + col) = make_float2(acc[mi][ni][2], acc[mi][ni][3]);
            }
        __syncthreads();

        // ---- fused gates: 16 rows per thread ----
        #pragma unroll 4
        for (int i = 0; i < 16; i++) {
            int row = rg * 16 + i;
            float pr  = ghs[row * 100 + jj]      + hxs[0 * 2048 + row * 32 + jj] + br_;
            float pu  = ghs[row * 100 + 32 + jj] + hxs[1 * 2048 + row * 32 + jj] + bu_;
            float pch = ghs[row * 100 + 64 + jj] + bc_;
            float xc  = hxs[2 * 2048 + row * 32 + jj];
            float hpv = hxs[3 * 2048 + row * 32 + jj];

            float rr = sigm(pr);
            float zz = sigm(pu);
            float nn = tanhf(xc + rr * pch);
            float hn = nn + zz * (hpv - nn);

            size_t gr = (size_t)(r0 + row) * ND + n0 + jj;
            hseq[(size_t)t * HN + gr] = hn;
            if (t == SEQ - 1) hlast[gr] = hn;
            __nv_bfloat16 hb = __float2bfloat16_rn(hn);
            g_hhi[gr] = hb;
            g_hlo[gr] = __float2bfloat16_rn(hn - __bfloat162float(hb));
        }

        // ---- grid barrier ----
        __syncthreads();
        if (tid == 0) {
            __threadfence();
            unsigned prev = atomicAdd(&g_bar_count, 1u);
            if (prev == NCTA - 1) {
                g_bar_count = 0;
                __threadfence();
                atomicAdd(&g_bar_gen, 1u);
            } else {
                unsigned target = (unsigned)t + 1u;
                while (*(volatile unsigned*)&g_bar_gen < target) { __nanosleep(32); }
            }
        }
        __syncthreads();
    }
}

// ============================================================================
extern "C" void kernel_launch(void* const* d_in, const int* in_sizes, int n_in,
                              void* d_out, int out_size)
{
    const float* x   = (const float*)d_in[0];
    const float* h0  = (const float*)d_in[1];
    const float* Wrx = (const float*)d_in[2];
    const float* brx = (const float*)d_in[3];
    const float* Wrh = (const float*)d_in[4];
    const float* brh = (const float*)d_in[5];
    const float* Wux = (const float*)d_in[6];
    const float* bux = (const float*)d_in[7];
    const float* Wuh = (const float*)d_in[8];
    const float* buh = (const float*)d_in[9];
    const float* Wcx = (const float*)d_in[10];
    const float* bcx = (const float*)d_in[11];
    const float* Wch = (const float*)d_in[12];
    const float* bch = (const float*)d_in[13];

    float* out   = (float*)d_out;
    float* hseq  = out;
    float* hlast = out + (size_t)SEQ * BATCH * ND;

    __nv_bfloat16 *axhi, *axlo, *wxhi, *wxlo, *wph, *wpl, *hhi, *hlo;
    cudaGetSymbolAddress((void**)&axhi, g_axhi);
    cudaGetSymbolAddress((void**)&axlo, g_axlo);
    cudaGetSymbolAddress((void**)&wxhi, g_wxhi);
    cudaGetSymbolAddress((void**)&wxlo, g_wxlo);
    cudaGetSymbolAddress((void**)&wph,  g_wph);
    cudaGetSymbolAddress((void**)&wpl,  g_wpl);
    cudaGetSymbolAddress((void**)&hhi,  g_hhi);
    cudaGetSymbolAddress((void**)&hlo,  g_hlo);

    // Phase 0: splits + weight packing.
    {
        int n4 = MX * KD / 4;
        split_bf16<<<(n4 + 255) / 256, 256>>>(x, axhi, axlo, n4);
        int w4 = ND * KD / 4;
        split_bf16<<<(w4 + 255) / 256, 256>>>(Wrx, wxhi, wxlo, w4);
        split_bf16<<<(w4 + 255) / 256, 256>>>(Wux, wxhi + (size_t)ND * KD,
                                              wxlo + (size_t)ND * KD, w4);
        split_bf16<<<(w4 + 255) / 256, 256>>>(Wcx, wxhi + (size_t)2 * ND * KD,
                                              wxlo + (size_t)2 * ND * KD, w4);
        pack_wh<<<(w4 + 255) / 256, 256>>>(Wrh, wph, wpl, 0);
        pack_wh<<<(w4 + 255) / 256, 256>>>(Wuh, wph, wpl, 1);
        pack_wh<<<(w4 + 255) / 256, 256>>>(Wch, wph, wpl, 2);
        int h4 = BATCH * KD / 4;
        split_bf16<<<(h4 + 255) / 256, 256>>>(h0, hhi, hlo, h4);
    }

    // Phase 1: HMMA x-projections (3 gates, split-bf16, fp32 accum).
    {
        const int smem_bytes = 2 * STG;
        cudaFuncSetAttribute(gemm_hmma,
                             cudaFuncAttributeMaxDynamicSharedMemorySize, smem_bytes);
        dim3 grid(ND / BNT, MX / BMT, 3);
        gemm_hmma<<<grid, 256, smem_bytes>>>(brx, bux, bcx);
    }

    // Phase 2: persistent HMMA recurrence.
    {
        cudaFuncSetAttribute(gru_persistent,
                             cudaFuncAttributeMaxDynamicSharedMemorySize, SM2_TOTAL);
        bar_init_kernel<<<1, 1>>>();
        gru_persistent<<<NCTA, 128, SM2_TOTAL>>>(h0, brh, buh, bch, hseq, hlast);
    }
}

// round 8
// speedup vs baseline: 3.0958x; 1.3149x over previous
#include <cuda_runtime.h>
#include <cuda_bf16.h>
#include <stdint.h>
#include <math.h>

#define SEQ    256
#define BATCH  256
#define KD     1024
#define ND     1024
#define MX     (SEQ * BATCH)
#define HN     (BATCH * ND)
#define NCTA   128

// ---------------- device scratch ------------------------------------------
static __device__ float          g_gx[(size_t)3 * MX * ND];
static __device__ __nv_bfloat16  g_axhi[(size_t)MX * KD];
static __device__ __nv_bfloat16  g_axlo[(size_t)MX * KD];
static __device__ __nv_bfloat16  g_wxhi[(size_t)3 * ND * KD];
static __device__ __nv_bfloat16  g_wxlo[(size_t)3 * ND * KD];
static __device__ __nv_bfloat16  g_wph[(size_t)3 * ND * KD];
static __device__ __nv_bfloat16  g_wpl[(size_t)3 * ND * KD];
static __device__ __nv_bfloat16  g_hhi[(size_t)BATCH * KD];
static __device__ __nv_bfloat16  g_hlo[(size_t)BATCH * KD];
static __device__ unsigned g_bar_count;
static __device__ unsigned g_bar_gen;

__device__ __forceinline__ uint32_t smem_u32(const void* p) {
    uint32_t a;
    asm("{ .reg .u64 t; cvta.to.shared.u64 t, %1; cvt.u32.u64 %0, t; }"
        : "=r"(a) : "l"(p));
    return a;
}
static __device__ __forceinline__ uint32_t sw128(uint32_t b) {
    return b ^ ((b >> 3) & 0x70);
}
__device__ __forceinline__ void ldsm4(uint32_t (&d)[4], uint32_t addr) {
    asm volatile("ldmatrix.sync.aligned.m8n8.x4.shared.b16 {%0,%1,%2,%3}, [%4];"
                 : "=r"(d[0]), "=r"(d[1]), "=r"(d[2]), "=r"(d[3]) : "r"(addr));
}
__device__ __forceinline__ void mma16816(float (&c)[4], const uint32_t (&a)[4],
                                         uint32_t b0, uint32_t b1) {
    asm volatile("mma.sync.aligned.m16n8k16.row.col.f32.bf16.bf16.f32 "
                 "{%0,%1,%2,%3}, {%4,%5,%6,%7}, {%8,%9}, {%0,%1,%2,%3};"
                 : "+f"(c[0]), "+f"(c[1]), "+f"(c[2]), "+f"(c[3])
                 : "r"(a[0]), "r"(a[1]), "r"(a[2]), "r"(a[3]), "r"(b0), "r"(b1));
}
__device__ __forceinline__ void cpa16(uint32_t smaddr, const void* g) {
    asm volatile("cp.async.cg.shared.global [%0], [%1], 16;" :: "r"(smaddr), "l"(g));
}
#define CPA_COMMIT() asm volatile("cp.async.commit_group;" ::: "memory")
template<int N> __device__ __forceinline__ void cp_wait() {
    asm volatile("cp.async.wait_group %0;" :: "n"(N) : "memory");
}
__device__ __forceinline__ float sigm(float v) { return 1.0f / (1.0f + expf(-v)); }

// ---------------- phase 0: splits / packing --------------------------------
__global__ __launch_bounds__(256)
void split_bf16(const float* __restrict__ src, __nv_bfloat16* __restrict__ hi,
                __nv_bfloat16* __restrict__ lo, int n4)
{
    int i = blockIdx.x * 256 + threadIdx.x;
    if (i >= n4) return;
    float4 v = ((const float4*)src)[i];
    __nv_bfloat16 h0 = __float2bfloat16_rn(v.x);
    __nv_bfloat16 h1 = __float2bfloat16_rn(v.y);
    __nv_bfloat16 h2 = __float2bfloat16_rn(v.z);
    __nv_bfloat16 h3 = __float2bfloat16_rn(v.w);
    __nv_bfloat16 l0 = __float2bfloat16_rn(v.x - __bfloat162float(h0));
    __nv_bfloat16 l1 = __float2bfloat16_rn(v.y - __bfloat162float(h1));
    __nv_bfloat16 l2 = __float2bfloat16_rn(v.z - __bfloat162float(h2));
    __nv_bfloat16 l3 = __float2bfloat16_rn(v.w - __bfloat162float(h3));
    __nv_bfloat162* hp = (__nv_bfloat162*)(hi + (size_t)i * 4);
    __nv_bfloat162* lp = (__nv_bfloat162*)(lo + (size_t)i * 4);
    hp[0] = __nv_bfloat162(h0, h1); hp[1] = __nv_bfloat162(h2, h3);
    lp[0] = __nv_bfloat162(l0, l1); lp[1] = __nv_bfloat162(l2, l3);
}

__global__ __launch_bounds__(256)
void pack_wh(const float* __restrict__ W, __nv_bfloat16* __restrict__ ph,
             __nv_bfloat16* __restrict__ pl, int g)
{
    int i = blockIdx.x * 256 + threadIdx.x;
    if (i >= ND * KD / 4) return;
    int n  = i >> 8;
    int k4 = i & 255;
    float4 v = *(const float4*)(W + (size_t)n * KD + k4 * 4);
    size_t drow = (size_t)((n >> 5) * 96 + g * 32 + (n & 31));
    __nv_bfloat16 h0 = __float2bfloat16_rn(v.x);
    __nv_bfloat16 h1 = __float2bfloat16_rn(v.y);
    __nv_bfloat16 h2 = __float2bfloat16_rn(v.z);
    __nv_bfloat16 h3 = __float2bfloat16_rn(v.w);
    __nv_bfloat16 l0 = __float2bfloat16_rn(v.x - __bfloat162float(h0));
    __nv_bfloat16 l1 = __float2bfloat16_rn(v.y - __bfloat162float(h1));
    __nv_bfloat16 l2 = __float2bfloat16_rn(v.z - __bfloat162float(h2));
    __nv_bfloat16 l3 = __float2bfloat16_rn(v.w - __bfloat162float(h3));
    __nv_bfloat162* hp = (__nv_bfloat162*)(ph + drow * KD + k4 * 4);
    __nv_bfloat162* lp = (__nv_bfloat162*)(pl + drow * KD + k4 * 4);
    hp[0] = __nv_bfloat162(h0, h1); hp[1] = __nv_bfloat162(h2, h3);
    lp[0] = __nv_bfloat162(l0, l1); lp[1] = __nv_bfloat162(l2, l3);
}

// ---------------- phase 1: HMMA GEMM, BM=128 BN=128, cp.async 3-stage -------
#define P1_STG 32768                     // stage: A 16K | B 16K

__global__ __launch_bounds__(256)
void gemm_hmma(const float* __restrict__ b0p, const float* __restrict__ b1p,
               const float* __restrict__ b2p)
{
    extern __shared__ char sm[];
    const uint32_t smb = smem_u32(sm);
    const int tid  = threadIdx.x;
    const int lane = tid & 31;
    const int w    = tid >> 5;
    const int wm   = w & 3;              // 4 m-blocks of 32
    const int wn   = w >> 2;             // 2 n-blocks of 64
    const int n0   = blockIdx.x * 128;
    const int m0   = blockIdx.y * 128;
    const int g    = blockIdx.z;

    const __nv_bfloat16* ahi = g_axhi + (size_t)m0 * KD;
    const __nv_bfloat16* alo = g_axlo + (size_t)m0 * KD;
    const __nv_bfloat16* whi = g_wxhi + (size_t)g * ND * KD + (size_t)n0 * KD;
    const __nv_bfloat16* wlo = g_wxlo + (size_t)g * ND * KD + (size_t)n0 * KD;

    auto issue = [&](int ck) {
        int p = ck >> 4, kb = (ck & 15) * 64;
        const __nv_bfloat16* As = (p < 2) ? ahi : alo;
        const __nv_bfloat16* Bs = (p == 1) ? wlo : whi;
        uint32_t stg = smb + (ck % 3) * P1_STG;
        #pragma unroll
        for (int i = 0; i < 4; i++) {
            int q = tid + i * 256; int row = q >> 3, kq = q & 7;
            cpa16(stg + sw128((uint32_t)(row * 128 + kq * 16)),
                  As + (size_t)row * KD + kb + kq * 8);
        }
        #pragma unroll
        for (int i = 0; i < 4; i++) {
            int q = tid + i * 256; int row = q >> 3, kq = q & 7;
            cpa16(stg + 16384 + sw128((uint32_t)(row * 128 + kq * 16)),
                  Bs + (size_t)row * KD + kb + kq * 8);
        }
        CPA_COMMIT();
    };

    float acc[2][8][4];
    #pragma unroll
    for (int mi = 0; mi < 2; mi++)
        #pragma unroll
        for (int ni = 0; ni < 8; ni++)
            #pragma unroll
            for (int q = 0; q < 4; q++) acc[mi][ni][q] = 0.0f;

    issue(0);
    issue(1);

    for (int it = 0; it < 48; it++) {
        if (it < 47) cp_wait<1>(); else cp_wait<0>();
        __syncthreads();
        if (it + 2 < 48) issue(it + 2);

        const uint32_t stg = smb + (it % 3) * P1_STG;
        #pragma unroll
        for (int kk = 0; kk < 4; kk++) {
            uint32_t af[2][4];
            {
                int tile = lane >> 3, r = lane & 7;
                int kb = kk * 32 + (tile >> 1) * 16;
                #pragma unroll
                for (int mi = 0; mi < 2; mi++) {
                    uint32_t sa = sw128((uint32_t)((wm * 32 + mi * 16 + (tile & 1) * 8 + r) * 128 + kb));
                    ldsm4(af[mi], stg + sa);
                }
            }
            uint32_t bfr[4][4];
            {
                int pair = lane >> 4, khalf = (lane >> 3) & 1, r = lane & 7;
                int kb = kk * 32 + khalf * 16;
                #pragma unroll
                for (int bp = 0; bp < 4; bp++) {
                    uint32_t sb = sw128((uint32_t)((wn * 64 + bp * 16 + pair * 8 + r) * 128 + kb));
                    ldsm4(bfr[bp], stg + 16384 + sb);
                }
            }
            #pragma unroll
            for (int mi = 0; mi < 2; mi++)
                #pragma unroll
                for (int ni = 0; ni < 8; ni++)
                    mma16816(acc[mi][ni], af[mi],
                             bfr[ni >> 1][(ni & 1) * 2], bfr[ni >> 1][(ni & 1) * 2 + 1]);
        }
    }

    const float* bias = (g == 0) ? b0p : (g == 1) ? b1p : b2p;
    float* C = g_gx + (size_t)g * MX * ND;
    #pragma unroll
    for (int ni = 0; ni < 8; ni++) {
        int col = n0 + wn * 64 + ni * 8 + (lane & 3) * 2;
        float2 bv = *(const float2*)(bias + col);
        #pragma unroll
        for (int mi = 0; mi < 2; mi++) {
            int row = m0 + wm * 32 + mi * 16 + (lane >> 2);
            float2 v0 = make_float2(acc[mi][ni][0] + bv.x, acc[mi][ni][1] + bv.y);
            float2 v1 = make_float2(acc[mi][ni][2] + bv.x, acc[mi][ni][3] + bv.y);
            *(float2*)(C + (size_t)row * ND + col)       = v0;
            *(float2*)(C + (size_t)(row + 8) * ND + col) = v1;
        }
    }
}

// ---------------- phase 2: persistent HMMA recurrence, 256 thr, 4 stages ----
#define RST    40960                     // AH 8K | AL 8K | BH 12K | BL 12K
#define OFF_AL 8192
#define OFF_BH 16384
#define OFF_BL 28672
#define GH_OFF (4 * RST)                 // fp32 gh tile [64][100]
#define HX_OFF (GH_OFF + 25600)         // fp32 [4][64][32]
#define SM2_TOTAL (HX_OFF + 32768)      // 222208 bytes

__global__ void bar_init_kernel() { g_bar_count = 0; g_bar_gen = 0; }

__global__ __launch_bounds__(256, 1)
void gru_persistent(const float* __restrict__ h0,
                    const float* __restrict__ brh, const float* __restrict__ buh,
                    const float* __restrict__ bch,
                    float* __restrict__ hseq, float* __restrict__ hlast)
{
    extern __shared__ char sm[];
    const uint32_t smb = smem_u32(sm);
    float* ghs = (float*)(sm + GH_OFF);
    float* hxs = (float*)(sm + HX_OFF);

    const int tid  = threadIdx.x;
    const int lane = tid & 31;
    const int w    = tid >> 5;
    const int wm   = w & 3;              // 4 m-blocks of 16 rows
    const int wn   = w >> 2;             // 2 n-blocks of 48 cols
    const int c    = blockIdx.x;
    const int r0   = (c & 3) * 64;
    const int jg   = c >> 2;
    const int n0   = jg * 32;

    const __nv_bfloat16* wph = g_wph + (size_t)(jg * 96) * KD;
    const __nv_bfloat16* wpl = g_wpl + (size_t)(jg * 96) * KD;
    const __nv_bfloat16* hhi = g_hhi + (size_t)r0 * KD;
    const __nv_bfloat16* hlo = g_hlo + (size_t)r0 * KD;

    const int jj = tid & 31;
    const float br_ = brh[n0 + jj], bu_ = buh[n0 + jj], bc_ = bch[n0 + jj];

    auto issue = [&](int ck) {
        uint32_t stg = smb + (ck & 3) * RST;
        int kb = ck * 64;
        #pragma unroll
        for (int i = 0; i < 2; i++) {
            int q = tid + i * 256; int row = q >> 3, kq = q & 7;
            uint32_t d = stg + sw128((uint32_t)(row * 128 + kq * 16));
            cpa16(d,          hhi + (size_t)row * KD + kb + kq * 8);
            cpa16(d + OFF_AL, hlo + (size_t)row * KD + kb + kq * 8);
        }
        #pragma unroll
        for (int i = 0; i < 3; i++) {
            int q = tid + i * 256; int row = q >> 3, kq = q & 7;
            uint32_t d = stg + OFF_BH + sw128((uint32_t)(row * 128 + kq * 16));
            cpa16(d,         wph + (size_t)row * KD + kb + kq * 8);
            cpa16(d + 12288, wpl + (size_t)row * KD + kb + kq * 8);
        }
        CPA_COMMIT();
    };

    float acc[6][4];

    for (int t = 0; t < SEQ; t++) {
        const float* hp = (t == 0) ? h0 : (hseq + (size_t)(t - 1) * HN);

        #pragma unroll
        for (int ni = 0; ni < 6; ni++)
            #pragma unroll
            for (int q = 0; q < 4; q++) acc[ni][q] = 0.0f;

        // ---- epilogue operands + chunk 0 (one group), then chunk 1 ----
        {
            uint32_t hxb = smb + HX_OFF;
            #pragma unroll
            for (int g = 0; g < 3; g++) {
                const float* src = g_gx + (size_t)g * MX * ND
                                 + ((size_t)t * BATCH + r0) * ND + n0;
                #pragma unroll
                for (int i = 0; i < 2; i++) {
                    int q = tid + i * 256; int row = q >> 3, j4 = q & 7;
                    cpa16(hxb + g * 8192 + row * 128 + j4 * 16,
                          src + (size_t)row * ND + j4 * 4);
                }
            }
            #pragma unroll
            for (int i = 0; i < 2; i++) {
                int q = tid + i * 256; int row = q >> 3, j4 = q & 7;
                cpa16(hxb + 3 * 8192 + row * 128 + j4 * 16,
                      hp + (size_t)(r0 + row) * ND + n0 + j4 * 4);
            }
        }
        issue(0);   // commits epi + chunk 0 together
        issue(1);

        // ---- K loop: 16 chunks of 64, 4 stages, 2-chunk lookahead ----
        for (int kt = 0; kt < 16; kt++) {
            if (kt + 2 < 16) issue(kt + 2);
            if (kt <= 13) cp_wait<2>();
            else if (kt == 14) cp_wait<1>();
            else cp_wait<0>();
            __syncthreads();

            const uint32_t stg = smb + (kt & 3) * RST;
            #pragma unroll
            for (int kk = 0; kk < 4; kk++) {
                uint32_t ah[4], al[4], bh[3][4], bl[3][4];
                {
                    int tile = lane >> 3, r = lane & 7;
                    int kb = kk * 32 + (tile >> 1) * 16;
                    uint32_t sa = sw128((uint32_t)((wm * 16 + (tile & 1) * 8 + r) * 128 + kb));
                    ldsm4(ah, stg + sa);
                    ldsm4(al, stg + OFF_AL + sa);
                }
                {
                    int pair = lane >> 4, khalf = (lane >> 3) & 1, r = lane & 7;
                    int kb = kk * 32 + khalf * 16;
                    #pragma unroll
                    for (int bp = 0; bp < 3; bp++) {
                        uint32_t sb = sw128((uint32_t)((wn * 48 + bp * 16 + pair * 8 + r) * 128 + kb));
                        ldsm4(bh[bp], stg + OFF_BH + sb);
                        ldsm4(bl[bp], stg + OFF_BL + sb);
                    }
                }
                #pragma unroll
                for (int ni = 0; ni < 6; ni++) {
                    uint32_t b0h = bh[ni >> 1][(ni & 1) * 2], b1h = bh[ni >> 1][(ni & 1) * 2 + 1];
                    uint32_t b0l = bl[ni >> 1][(ni & 1) * 2], b1l = bl[ni >> 1][(ni & 1) * 2 + 1];
                    mma16816(acc[ni], ah, b0h, b1h);
                    mma16816(acc[ni], al, b0h, b1h);
                    mma16816(acc[ni], ah, b0l, b1l);
                }
            }
        }

        // ---- dump accumulators to smem tile [64][100] ----
        #pragma unroll
        for (int ni = 0; ni < 6; ni++) {
            int col = wn * 48 + ni * 8 + (lane & 3) * 2;
            int row = wm * 16 + (lane >> 2);
            *(float2*)(ghs + row * 100 + col)       = make_float2(acc[ni][0], acc[ni][1]);
            *(float2*)(ghs + (row + 8) * 100 + col) = make_float2(acc[ni][2], acc[ni][3]);
        }
        __syncthreads();

        // ---- fused gates: 8 rows per thread ----
        #pragma unroll 4
        for (int i = 0; i < 8; i++) {
            int row = (tid >> 5) * 8 + i;
            float pr  = ghs[row * 100 + jj]      + hxs[0 * 2048 + row * 32 + jj] + br_;
            float pu  = ghs[row * 100 + 32 + jj] + hxs[1 * 2048 + row * 32 + jj] + bu_;
            float pch = ghs[row * 100 + 64 + jj] + bc_;
            float xc  = hxs[2 * 2048 + row * 32 + jj];
            float hpv = hxs[3 * 2048 + row * 32 + jj];

            float rr = sigm(pr);
            float zz = sigm(pu);
            float nn = tanhf(xc + rr * pch);
            float hn = nn + zz * (hpv - nn);

            size_t gr = (size_t)(r0 + row) * ND + n0 + jj;
            hseq[(size_t)t * HN + gr] = hn;
            if (t == SEQ - 1) hlast[gr] = hn;
            __nv_bfloat16 hb = __float2bfloat16_rn(hn);
            g_hhi[gr] = hb;
            g_hlo[gr] = __float2bfloat16_rn(hn - __bfloat162float(hb));
        }

        // ---- grid barrier ----
        __syncthreads();
        if (tid == 0) {
            __threadfence();
            unsigned prev = atomicAdd(&g_bar_count, 1u);
            if (prev == NCTA - 1) {
                g_bar_count = 0;
                __threadfence();
                atomicAdd(&g_bar_gen, 1u);
            } else {
                unsigned target = (unsigned)t + 1u;
                while (*(volatile unsigned*)&g_bar_gen < target) { __nanosleep(32); }
            }
        }
        __syncthreads();
    }
}

// ============================================================================
extern "C" void kernel_launch(void* const* d_in, const int* in_sizes, int n_in,
                              void* d_out, int out_size)
{
    const float* x   = (const float*)d_in[0];
    const float* h0  = (const float*)d_in[1];
    const float* Wrx = (const float*)d_in[2];
    const float* brx = (const float*)d_in[3];
    const float* Wrh = (const float*)d_in[4];
    const float* brh = (const float*)d_in[5];
    const float* Wux = (const float*)d_in[6];
    const float* bux = (const float*)d_in[7];
    const float* Wuh = (const float*)d_in[8];
    const float* buh = (const float*)d_in[9];
    const float* Wcx = (const float*)d_in[10];
    const float* bcx = (const float*)d_in[11];
    const float* Wch = (const float*)d_in[12];
    const float* bch = (const float*)d_in[13];

    float* out   = (float*)d_out;
    float* hseq  = out;
    float* hlast = out + (size_t)SEQ * BATCH * ND;

    __nv_bfloat16 *axhi, *axlo, *wxhi, *wxlo, *wph, *wpl, *hhi, *hlo;
    cudaGetSymbolAddress((void**)&axhi, g_axhi);
    cudaGetSymbolAddress((void**)&axlo, g_axlo);
    cudaGetSymbolAddress((void**)&wxhi, g_wxhi);
    cudaGetSymbolAddress((void**)&wxlo, g_wxlo);
    cudaGetSymbolAddress((void**)&wph,  g_wph);
    cudaGetSymbolAddress((void**)&wpl,  g_wpl);
    cudaGetSymbolAddress((void**)&hhi,  g_hhi);
    cudaGetSymbolAddress((void**)&hlo,  g_hlo);

    // Phase 0: splits + weight packing.
    {
        int n4 = MX * KD / 4;
        split_bf16<<<(n4 + 255) / 256, 256>>>(x, axhi, axlo, n4);
        int w4 = ND * KD / 4;
        split_bf16<<<(w4 + 255) / 256, 256>>>(Wrx, wxhi, wxlo, w4);
        split_bf16<<<(w4 + 255) / 256, 256>>>(Wux, wxhi + (size_t)ND * KD,
                                              wxlo + (size_t)ND * KD, w4);
        split_bf16<<<(w4 + 255) / 256, 256>>>(Wcx, wxhi + (size_t)2 * ND * KD,
                                              wxlo + (size_t)2 * ND * KD, w4);
        pack_wh<<<(w4 + 255) / 256, 256>>>(Wrh, wph, wpl, 0);
        pack_wh<<<(w4 + 255) / 256, 256>>>(Wuh, wph, wpl, 1);
        pack_wh<<<(w4 + 255) / 256, 256>>>(Wch, wph, wpl, 2);
        int h4 = BATCH * KD / 4;
        split_bf16<<<(h4 + 255) / 256, 256>>>(h0, hhi, hlo, h4);
    }

    // Phase 1: HMMA x-projections (128x128 tiles, cp.async pipeline).
    {
        const int smem_bytes = 3 * P1_STG;   // 98304
        cudaFuncSetAttribute(gemm_hmma,
                             cudaFuncAttributeMaxDynamicSharedMemorySize, smem_bytes);
        dim3 grid(ND / 128, MX / 128, 3);
        gemm_hmma<<<grid, 256, smem_bytes>>>(brx, bux, bcx);
    }

    // Phase 2: persistent HMMA recurrence (256 threads, 4-stage pipeline).
    {
        cudaFuncSetAttribute(gru_persistent,
                             cudaFuncAttributeMaxDynamicSharedMemorySize, SM2_TOTAL);
        bar_init_kernel<<<1, 1>>>();
        gru_persistent<<<NCTA, 256, SM2_TOTAL>>>(h0, brh, buh, bch, hseq, hlast);
    }
}

// round 11
// speedup vs baseline: 3.1021x; 1.0020x over previous
#include <cuda_runtime.h>
#include <cuda_bf16.h>
#include <stdint.h>
#include <math.h>

#define SEQ    256
#define BATCH  256
#define KD     1024
#define ND     1024
#define MX     (SEQ * BATCH)
#define HN     (BATCH * ND)
#define NCTA   128

// ---------------- device scratch ------------------------------------------
static __device__ float          g_gx[(size_t)3 * MX * ND];
static __device__ __nv_bfloat16  g_axhi[(size_t)MX * KD];
static __device__ __nv_bfloat16  g_axlo[(size_t)MX * KD];
static __device__ __nv_bfloat16  g_wxhi[(size_t)3 * ND * KD];
static __device__ __nv_bfloat16  g_wxlo[(size_t)3 * ND * KD];
static __device__ __nv_bfloat16  g_wph[(size_t)3 * ND * KD];
static __device__ __nv_bfloat16  g_wpl[(size_t)3 * ND * KD];
static __device__ __nv_bfloat16  g_hhi[(size_t)BATCH * KD];
static __device__ __nv_bfloat16  g_hlo[(size_t)BATCH * KD];
// 4 independent group barriers (one per m-block), 128B padding between slots
static __device__ unsigned g_cntArr[128];
static __device__ unsigned g_genArr[128];

__device__ __forceinline__ uint32_t smem_u32(const void* p) {
    uint32_t a;
    asm("{ .reg .u64 t; cvta.to.shared.u64 t, %1; cvt.u32.u64 %0, t; }"
        : "=r"(a) : "l"(p));
    return a;
}
static __device__ __forceinline__ uint32_t sw128(uint32_t b) {
    return b ^ ((b >> 3) & 0x70);
}
__device__ __forceinline__ void ldsm4(uint32_t (&d)[4], uint32_t addr) {
    asm volatile("ldmatrix.sync.aligned.m8n8.x4.shared.b16 {%0,%1,%2,%3}, [%4];"
                 : "=r"(d[0]), "=r"(d[1]), "=r"(d[2]), "=r"(d[3]) : "r"(addr));
}
__device__ __forceinline__ void mma16816(float (&c)[4], const uint32_t (&a)[4],
                                         uint32_t b0, uint32_t b1) {
    asm volatile("mma.sync.aligned.m16n8k16.row.col.f32.bf16.bf16.f32 "
                 "{%0,%1,%2,%3}, {%4,%5,%6,%7}, {%8,%9}, {%0,%1,%2,%3};"
                 : "+f"(c[0]), "+f"(c[1]), "+f"(c[2]), "+f"(c[3])
                 : "r"(a[0]), "r"(a[1]), "r"(a[2]), "r"(a[3]), "r"(b0), "r"(b1));
}
__device__ __forceinline__ void cpa16(uint32_t smaddr, const void* g) {
    asm volatile("cp.async.cg.shared.global [%0], [%1], 16;" :: "r"(smaddr), "l"(g));
}
#define CPA_COMMIT() asm volatile("cp.async.commit_group;" ::: "memory")
template<int N> __device__ __forceinline__ void cp_wait() {
    asm volatile("cp.async.wait_group %0;" :: "n"(N) : "memory");
}
__device__ __forceinline__ float sigm(float v) { return 1.0f / (1.0f + expf(-v)); }

// ---------------- phase 0: splits / packing --------------------------------
__device__ __forceinline__ void split4(float4 v, __nv_bfloat16* hi,
                                       __nv_bfloat16* lo, size_t idx4) {
    __nv_bfloat16 h0 = __float2bfloat16_rn(v.x);
    __nv_bfloat16 h1 = __float2bfloat16_rn(v.y);
    __nv_bfloat16 h2 = __float2bfloat16_rn(v.z);
    __nv_bfloat16 h3 = __float2bfloat16_rn(v.w);
    __nv_bfloat16 l0 = __float2bfloat16_rn(v.x - __bfloat162float(h0));
    __nv_bfloat16 l1 = __float2bfloat16_rn(v.y - __bfloat162float(h1));
    __nv_bfloat16 l2 = __float2bfloat16_rn(v.z - __bfloat162float(h2));
    __nv_bfloat16 l3 = __float2bfloat16_rn(v.w - __bfloat162float(h3));
    __nv_bfloat162* hp = (__nv_bfloat162*)(hi + idx4 * 4);
    __nv_bfloat162* lp = (__nv_bfloat162*)(lo + idx4 * 4);
    hp[0] = __nv_bfloat162(h0, h1); hp[1] = __nv_bfloat162(h2, h3);
    lp[0] = __nv_bfloat162(l0, l1); lp[1] = __nv_bfloat162(l2, l3);
}

__global__ __launch_bounds__(256)
void split_bf16(const float* __restrict__ src, __nv_bfloat16* __restrict__ hi,
                __nv_bfloat16* __restrict__ lo, int n4)
{
    int i = blockIdx.x * 256 + threadIdx.x;
    if (i >= n4) return;
    split4(((const float4*)src)[i], hi, lo, (size_t)i);
}

// three x-weight splits fused (gate-major contiguous destination)
__global__ __launch_bounds__(256)
void split3_w(const float* __restrict__ W0, const float* __restrict__ W1,
              const float* __restrict__ W2,
              __nv_bfloat16* __restrict__ hi, __nv_bfloat16* __restrict__ lo)
{
    const int per = ND * KD / 4;
    int i = blockIdx.x * 256 + threadIdx.x;
    if (i >= 3 * per) return;
    int g = i / per, r = i - g * per;
    const float* W = (g == 0) ? W0 : (g == 1) ? W1 : W2;
    split4(*(const float4*)(W + (size_t)r * 4), hi, lo, (size_t)i);
}

// three h-weight packs fused: [jg][3*32 rows][1024 k], split hi/lo
__global__ __launch_bounds__(256)
void pack3_wh(const float* __restrict__ W0, const float* __restrict__ W1,
              const float* __restrict__ W2,
              __nv_bfloat16* __restrict__ ph, __nv_bfloat16* __restrict__ pl)
{
    const int per = ND * KD / 4;
    int i = blockIdx.x * 256 + threadIdx.x;
    if (i >= 3 * per) return;
    int g = i / per, r = i - g * per;
    const float* W = (g == 0) ? W0 : (g == 1) ? W1 : W2;
    int n  = r >> 8;
    int k4 = r & 255;
    float4 v = *(const float4*)(W + (size_t)n * KD + k4 * 4);
    size_t drow = (size_t)((n >> 5) * 96 + g * 32 + (n & 31));
    split4(v, ph, pl, drow * (KD / 4) + k4);
}

// ---------------- phase 1: HMMA GEMM, BM=128 BN=128, cp.async 3-stage -------
#define P1_STG 32768

__global__ __launch_bounds__(256)
void gemm_hmma(const float* __restrict__ b0p, const float* __restrict__ b1p,
               const float* __restrict__ b2p)
{
    extern __shared__ char sm[];
    const uint32_t smb = smem_u32(sm);
    const int tid  = threadIdx.x;
    const int lane = tid & 31;
    const int w    = tid >> 5;
    const int wm   = w & 3;
    const int wn   = w >> 2;
    const int n0   = blockIdx.x * 128;
    const int m0   = blockIdx.y * 128;
    const int g    = blockIdx.z;

    const __nv_bfloat16* ahi = g_axhi + (size_t)m0 * KD;
    const __nv_bfloat16* alo = g_axlo + (size_t)m0 * KD;
    const __nv_bfloat16* whi = g_wxhi + (size_t)g * ND * KD + (size_t)n0 * KD;
    const __nv_bfloat16* wlo = g_wxlo + (size_t)g * ND * KD + (size_t)n0 * KD;

    auto issue = [&](int ck) {
        int p = ck >> 4, kb = (ck & 15) * 64;
        const __nv_bfloat16* As = (p < 2) ? ahi : alo;
        const __nv_bfloat16* Bs = (p == 1) ? wlo : whi;
        uint32_t stg = smb + (ck % 3) * P1_STG;
        #pragma unroll
        for (int i = 0; i < 4; i++) {
            int q = tid + i * 256; int row = q >> 3, kq = q & 7;
            cpa16(stg + sw128((uint32_t)(row * 128 + kq * 16)),
                  As + (size_t)row * KD + kb + kq * 8);
        }
        #pragma unroll
        for (int i = 0; i < 4; i++) {
            int q = tid + i * 256; int row = q >> 3, kq = q & 7;
            cpa16(stg + 16384 + sw128((uint32_t)(row * 128 + kq * 16)),
                  Bs + (size_t)row * KD + kb + kq * 8);
        }
        CPA_COMMIT();
    };

    float acc[2][8][4];
    #pragma unroll
    for (int mi = 0; mi < 2; mi++)
        #pragma unroll
        for (int ni = 0; ni < 8; ni++)
            #pragma unroll
            for (int q = 0; q < 4; q++) acc[mi][ni][q] = 0.0f;

    issue(0);
    issue(1);

    for (int it = 0; it < 48; it++) {
        if (it < 47) cp_wait<1>(); else cp_wait<0>();
        __syncthreads();
        if (it + 2 < 48) issue(it + 2);

        const uint32_t stg = smb + (it % 3) * P1_STG;
        #pragma unroll
        for (int kk = 0; kk < 4; kk++) {
            uint32_t af[2][4];
            {
                int tile = lane >> 3, r = lane & 7;
                int kb = kk * 32 + (tile >> 1) * 16;
                #pragma unroll
                for (int mi = 0; mi < 2; mi++) {
                    uint32_t sa = sw128((uint32_t)((wm * 32 + mi * 16 + (tile & 1) * 8 + r) * 128 + kb));
                    ldsm4(af[mi], stg + sa);
                }
            }
            uint32_t bfr[4][4];
            {
                int pair = lane >> 4, khalf = (lane >> 3) & 1, r = lane & 7;
                int kb = kk * 32 + khalf * 16;
                #pragma unroll
                for (int bp = 0; bp < 4; bp++) {
                    uint32_t sb = sw128((uint32_t)((wn * 64 + bp * 16 + pair * 8 + r) * 128 + kb));
                    ldsm4(bfr[bp], stg + 16384 + sb);
                }
            }
            #pragma unroll
            for (int mi = 0; mi < 2; mi++)
                #pragma unroll
                for (int ni = 0; ni < 8; ni++)
                    mma16816(acc[mi][ni], af[mi],
                             bfr[ni >> 1][(ni & 1) * 2], bfr[ni >> 1][(ni & 1) * 2 + 1]);
        }
    }

    const float* bias = (g == 0) ? b0p : (g == 1) ? b1p : b2p;
    float* C = g_gx + (size_t)g * MX * ND;
    #pragma unroll
    for (int ni = 0; ni < 8; ni++) {
        int col = n0 + wn * 64 + ni * 8 + (lane & 3) * 2;
        float2 bv = *(const float2*)(bias + col);
        #pragma unroll
        for (int mi = 0; mi < 2; mi++) {
            int row = m0 + wm * 32 + mi * 16 + (lane >> 2);
            float2 v0 = make_float2(acc[mi][ni][0] + bv.x, acc[mi][ni][1] + bv.y);
            float2 v1 = make_float2(acc[mi][ni][2] + bv.x, acc[mi][ni][3] + bv.y);
            *(float2*)(C + (size_t)row * ND + col)       = v0;
            *(float2*)(C + (size_t)(row + 8) * ND + col) = v1;
        }
    }
}

// ---------------- phase 2: persistent HMMA recurrence -----------------------
#define RST    40960
#define OFF_AL 8192
#define OFF_BH 16384
#define OFF_BL 28672
#define GH_OFF (4 * RST)
#define HX_OFF (GH_OFF + 25600)
#define SM2_TOTAL (HX_OFF + 32768)

__global__ void bar_init_kernel() {
    #pragma unroll
    for (int i = 0; i < 4; i++) { g_cntArr[i * 32] = 0; g_genArr[i * 32] = 0; }
}

__global__ __launch_bounds__(256, 1)
void gru_persistent(const float* __restrict__ h0,
                    const float* __restrict__ brh, const float* __restrict__ buh,
                    const float* __restrict__ bch,
                    float* __restrict__ hseq, float* __restrict__ hlast)
{
    extern __shared__ char sm[];
    const uint32_t smb = smem_u32(sm);
    float* ghs = (float*)(sm + GH_OFF);
    float* hxs = (float*)(sm + HX_OFF);

    const int tid  = threadIdx.x;
    const int lane = tid & 31;
    const int w    = tid >> 5;
    const int wm   = w & 3;
    const int wn   = w >> 2;
    const int c    = blockIdx.x;
    const int mb   = c & 3;              // barrier group = m-block
    const int r0   = mb * 64;
    const int jg   = c >> 2;
    const int n0   = jg * 32;

    const __nv_bfloat16* wph = g_wph + (size_t)(jg * 96) * KD;
    const __nv_bfloat16* wpl = g_wpl + (size_t)(jg * 96) * KD;
    const __nv_bfloat16* hhi = g_hhi + (size_t)r0 * KD;
    const __nv_bfloat16* hlo = g_hlo + (size_t)r0 * KD;

    const int jj = tid & 31;
    const float br_ = brh[n0 + jj], bu_ = buh[n0 + jj], bc_ = bch[n0 + jj];

    // full chunk (h + W) for ck >= 2
    auto issue = [&](int ck) {
        uint32_t stg = smb + (ck & 3) * RST;
        int kb = ck * 64;
        #pragma unroll
        for (int i = 0; i < 2; i++) {
            int q = tid + i * 256; int row = q >> 3, kq = q & 7;
            uint32_t d = stg + sw128((uint32_t)(row * 128 + kq * 16));
            cpa16(d,          hhi + (size_t)row * KD + kb + kq * 8);
            cpa16(d + OFF_AL, hlo + (size_t)row * KD + kb + kq * 8);
        }
        #pragma unroll
        for (int i = 0; i < 3; i++) {
            int q = tid + i * 256; int row = q >> 3, kq = q & 7;
            uint32_t d = stg + OFF_BH + sw128((uint32_t)(row * 128 + kq * 16));
            cpa16(d,         wph + (size_t)row * KD + kb + kq * 8);
            cpa16(d + 12288, wpl + (size_t)row * KD + kb + kq * 8);
        }
        CPA_COMMIT();
    };

    // W-only prefetch for chunks 0,1 (h-independent -> issued BEFORE barrier)
    auto issueW01 = [&]() {
        #pragma unroll
        for (int s = 0; s < 2; s++) {
            uint32_t stg = smb + s * RST;
            int kb = s * 64;
            #pragma unroll
            for (int i = 0; i < 3; i++) {
                int q = tid + i * 256; int row = q >> 3, kq = q & 7;
                uint32_t d = stg + OFF_BH + sw128((uint32_t)(row * 128 + kq * 16));
                cpa16(d,         wph + (size_t)row * KD + kb + kq * 8);
                cpa16(d + 12288, wpl + (size_t)row * KD + kb + kq * 8);
            }
        }
        CPA_COMMIT();
    };

    float acc[6][4];

    issueW01();                          // W for step-0 chunks 0,1

    for (int t = 0; t < SEQ; t++) {
        const float* hp = (t == 0) ? h0 : (hseq + (size_t)(t - 1) * HN);

        #pragma unroll
        for (int ni = 0; ni < 6; ni++)
            #pragma unroll
            for (int q = 0; q < 4; q++) acc[ni][q] = 0.0f;

        // ---- group G_h0: h chunk 0 (AH/AL) + epilogue operands ----
        {
            uint32_t stg = smb;
            #pragma unroll
            for (int i = 0; i < 2; i++) {
                int q = tid + i * 256; int row = q >> 3, kq = q & 7;
                uint32_t d = stg + sw128((uint32_t)(row * 128 + kq * 16));
                cpa16(d,          hhi + (size_t)row * KD + kq * 8);
                cpa16(d + OFF_AL, hlo + (size_t)row * KD + kq * 8);
            }
            uint32_t hxb = smb + HX_OFF;
            #pragma unroll
            for (int g = 0; g < 3; g++) {
                const float* src = g_gx + (size_t)g * MX * ND
                                 + ((size_t)t * BATCH + r0) * ND + n0;
                #pragma unroll
                for (int i = 0; i < 2; i++) {
                    int q = tid + i * 256; int row = q >> 3, j4 = q & 7;
                    cpa16(hxb + g * 8192 + row * 128 + j4 * 16,
                          src + (size_t)row * ND + j4 * 4);
                }
            }
            #pragma unroll
            for (int i = 0; i < 2; i++) {
                int q = tid + i * 256; int row = q >> 3, j4 = q & 7;
                cpa16(hxb + 3 * 8192 + row * 128 + j4 * 16,
                      hp + (size_t)(r0 + row) * ND + n0 + j4 * 4);
            }
            CPA_COMMIT();
        }
        // ---- group G_h1: h chunk 1 (AH/AL) ----
        {
            uint32_t stg = smb + RST;
            #pragma unroll
            for (int i = 0; i < 2; i++) {
                int q = tid + i * 256; int row = q >> 3, kq = q & 7;
                uint32_t d = stg + sw128((uint32_t)(row * 128 + kq * 16));
                cpa16(d,          hhi + (size_t)row * KD + 64 + kq * 8);
                cpa16(d + OFF_AL, hlo + (size_t)row * KD + 64 + kq * 8);
            }
            CPA_COMMIT();
        }

        // ---- K loop: 16 chunks of 64, 4 stages ----
        for (int kt = 0; kt < 16; kt++) {
            if (kt + 2 < 16) issue(kt + 2);
            if (kt <= 13) cp_wait<2>();
            else if (kt == 14) cp_wait<1>();
            else cp_wait<0>();
            __syncthreads();

            const uint32_t stg = smb + (kt & 3) * RST;
            #pragma unroll
            for (int kk = 0; kk < 4; kk++) {
                uint32_t ah[4], al[4], bh[3][4], bl[3][4];
                {
                    int tile = lane >> 3, r = lane & 7;
                    int kb = kk * 32 + (tile >> 1) * 16;
                    uint32_t sa = sw128((uint32_t)((wm * 16 + (tile & 1) * 8 + r) * 128 + kb));
                    ldsm4(ah, stg + sa);
                    ldsm4(al, stg + OFF_AL + sa);
                }
                {
                    int pair = lane >> 4, khalf = (lane >> 3) & 1, r = lane & 7;
                    int kb = kk * 32 + khalf * 16;
                    #pragma unroll
                    for (int bp = 0; bp < 3; bp++) {
                        uint32_t sb = sw128((uint32_t)((wn * 48 + bp * 16 + pair * 8 + r) * 128 + kb));
                        ldsm4(bh[bp], stg + OFF_BH + sb);
                        ldsm4(bl[bp], stg + OFF_BL + sb);
                    }
                }
                #pragma unroll
                for (int ni = 0; ni < 6; ni++) {
                    uint32_t b0h = bh[ni >> 1][(ni & 1) * 2], b1h = bh[ni >> 1][(ni & 1) * 2 + 1];
                    uint32_t b0l = bl[ni >> 1][(ni & 1) * 2], b1l = bl[ni >> 1][(ni & 1) * 2 + 1];
                    mma16816(acc[ni], ah, b0h, b1h);
                    mma16816(acc[ni], al, b0h, b1h);
                    mma16816(acc[ni], ah, b0l, b1l);
                }
            }
        }

        // ---- dump accumulators to smem tile [64][100] ----
        #pragma unroll
        for (int ni = 0; ni < 6; ni++) {
            int col = wn * 48 + ni * 8 + (lane & 3) * 2;
            int row = wm * 16 + (lane >> 2);
            *(float2*)(ghs + row * 100 + col)       = make_float2(acc[ni][0], acc[ni][1]);
            *(float2*)(ghs + (row + 8) * 100 + col) = make_float2(acc[ni][2], acc[ni][3]);
        }
        __syncthreads();

        // ---- fused gates: 8 rows per thread ----
        #pragma unroll 4
        for (int i = 0; i < 8; i++) {
            int row = (tid >> 5) * 8 + i;
            float pr  = ghs[row * 100 + jj]      + hxs[0 * 2048 + row * 32 + jj] + br_;
            float pu  = ghs[row * 100 + 32 + jj] + hxs[1 * 2048 + row * 32 + jj] + bu_;
            float pch = ghs[row * 100 + 64 + jj] + bc_;
            float xc  = hxs[2 * 2048 + row * 32 + jj];
            float hpv = hxs[3 * 2048 + row * 32 + jj];

            float rr = sigm(pr);
            float zz = sigm(pu);
            float nn = tanhf(xc + rr * pch);
            float hn = nn + zz * (hpv - nn);

            size_t gr = (size_t)(r0 + row) * ND + n0 + jj;
            hseq[(size_t)t * HN + gr] = hn;
            if (t == SEQ - 1) hlast[gr] = hn;
            __nv_bfloat16 hb = __float2bfloat16_rn(hn);
            g_hhi[gr] = hb;
            g_hlo[gr] = __float2bfloat16_rn(hn - __bfloat162float(hb));
        }

        // ---- prefetch next step's W chunks 0,1 (h-independent) ----
        __syncthreads();                 // all reads of stages 0,1 + hxs done
        issueW01();

        // ---- group barrier (32 CTAs sharing this m-block) ----
        if (tid == 0) {
            __threadfence();
            unsigned prev = atomicAdd(&g_cntArr[mb * 32], 1u);
            if (prev == 31u) {
                g_cntArr[mb * 32] = 0;
                __threadfence();
                atomicAdd(&g_genArr[mb * 32], 1u);
            } else {
                unsigned target = (unsigned)t + 1u;
                while (*(volatile unsigned*)&g_genArr[mb * 32] < target)
                    __nanosleep(20);
            }
        }
        __syncthreads();
    }
}

// ============================================================================
extern "C" void kernel_launch(void* const* d_in, const int* in_sizes, int n_in,
                              void* d_out, int out_size)
{
    const float* x   = (const float*)d_in[0];
    const float* h0  = (const float*)d_in[1];
    const float* Wrx = (const float*)d_in[2];
    const float* brx = (const float*)d_in[3];
    const float* Wrh = (const float*)d_in[4];
    const float* brh = (const float*)d_in[5];
    const float* Wux = (const float*)d_in[6];
    const float* bux = (const float*)d_in[7];
    const float* Wuh = (const float*)d_in[8];
    const float* buh = (const float*)d_in[9];
    const float* Wcx = (const float*)d_in[10];
    const float* bcx = (const float*)d_in[11];
    const float* Wch = (const float*)d_in[12];
    const float* bch = (const float*)d_in[13];

    float* out   = (float*)d_out;
    float* hseq  = out;
    float* hlast = out + (size_t)SEQ * BATCH * ND;

    __nv_bfloat16 *axhi, *axlo, *wxhi, *wxlo, *wph, *wpl, *hhi, *hlo;
    cudaGetSymbolAddress((void**)&axhi, g_axhi);
    cudaGetSymbolAddress((void**)&axlo, g_axlo);
    cudaGetSymbolAddress((void**)&wxhi, g_wxhi);
    cudaGetSymbolAddress((void**)&wxlo, g_wxlo);
    cudaGetSymbolAddress((void**)&wph,  g_wph);
    cudaGetSymbolAddress((void**)&wpl,  g_wpl);
    cudaGetSymbolAddress((void**)&hhi,  g_hhi);
    cudaGetSymbolAddress((void**)&hlo,  g_hlo);

    // Phase 0: splits + weight packing (fused).
    {
        int n4 = MX * KD / 4;
        split_bf16<<<(n4 + 255) / 256, 256>>>(x, axhi, axlo, n4);
        int w12 = 3 * ND * KD / 4;
        split3_w<<<(w12 + 255) / 256, 256>>>(Wrx, Wux, Wcx, wxhi, wxlo);
        pack3_wh<<<(w12 + 255) / 256, 256>>>(Wrh, Wuh, Wch, wph, wpl);
        int h4 = BATCH * KD / 4;
        split_bf16<<<(h4 + 255) / 256, 256>>>(h0, hhi, hlo, h4);
    }

    // Phase 1: HMMA x-projections.
    {
        const int smem_bytes = 3 * P1_STG;
        cudaFuncSetAttribute(gemm_hmma,
                             cudaFuncAttributeMaxDynamicSharedMemorySize, smem_bytes);
        dim3 grid(ND / 128, MX / 128, 3);
        gemm_hmma<<<grid, 256, smem_bytes>>>(brx, bux, bcx);
    }

    // Phase 2: persistent HMMA recurrence (4 independent barrier groups).
    {
        cudaFuncSetAttribute(gru_persistent,
                             cudaFuncAttributeMaxDynamicSharedMemorySize, SM2_TOTAL);
        bar_init_kernel<<<1, 1>>>();
        gru_persistent<<<NCTA, 256, SM2_TOTAL>>>(h0, brh, buh, bch, hseq, hlast);
    }
}